// round 9
// baseline (speedup 1.0000x reference)
#include <cuda_runtime.h>
#include <cuda_fp16.h>
#include <cstddef>

#define HEADS  8
#define NNODES 8192
#define NEDGES 131072
#define NEG    0.2f

typedef unsigned long long ull;

// ---------------- scratch (static __device__, no allocation) ----------------
__device__ float  g_h1lin[NNODES*64];
__device__ float  g_as1[NNODES*HEADS];
__device__ float  g_ad1[NNODES*HEADS];
__device__ float  g_h1[NNODES*64];
__device__ __half g_h2lin_h[(size_t)NNODES*1024];  // 16MB fp16 interchange
__device__ __half g_h2h[(size_t)NNODES*1024];      // 16MB fp16 interchange
__device__ float  g_as2[NNODES*HEADS];
__device__ float  g_ad2[NNODES*HEADS];
__device__ int    g_deg[NNODES];
__device__ int    g_rowptr[NNODES+1];
__device__ int    g_cursor[NNODES];
__device__ int    g_srcs[NEDGES];
__device__ int    g_is64;
__device__ float  g_Ms[64*8];
__device__ float  g_Md[64*8];
__device__ float  g_valacc[512];
__device__ float  g_advacc[128];

struct h4 { __half2 a, b; };

__device__ __forceinline__ float lrelu(float x){ return x > 0.f ? x : NEG*x; }

__device__ __forceinline__ void shfl_add(float4& v, int off){
    v.x += __shfl_down_sync(~0u, v.x, off);
    v.y += __shfl_down_sync(~0u, v.y, off);
    v.z += __shfl_down_sync(~0u, v.z, off);
    v.w += __shfl_down_sync(~0u, v.w, off);
}

// ---- packed fp32x2 helpers (Blackwell) ----
__device__ __forceinline__ ull pack2(float lo, float hi){
    ull r;
    asm("mov.b64 %0, {%1, %2};" : "=l"(r) : "r"(__float_as_uint(lo)), "r"(__float_as_uint(hi)));
    return r;
}
__device__ __forceinline__ void unpack2(ull v, float& lo, float& hi){
    unsigned int a, b;
    asm("mov.b64 {%0, %1}, %2;" : "=r"(a), "=r"(b) : "l"(v));
    lo = __uint_as_float(a); hi = __uint_as_float(b);
}
__device__ __forceinline__ void fma2(ull& d, ull a, ull b){
    asm("fma.rn.f32x2 %0, %1, %2, %0;" : "+l"(d) : "l"(a), "l"(b));
}

// ---------------- prep0: dtype sniff + zeroing ----------------
__global__ __launch_bounds__(512) void prep0_kernel(const int* __restrict__ e32){
    int t = threadIdx.x;
    __shared__ int nz;
    if (t == 0) nz = 0;
    __syncthreads();
    int v = 0;
    for (int i = t; i < 8192; i += 512) v |= e32[2*i+1];
    if (v) atomicOr(&nz, 1);
    for (int i = t; i < NNODES; i += 512) g_deg[i] = 0;
    g_valacc[t] = 0.f;
    if (t < 128) g_advacc[t] = 0.f;
    __syncthreads();
    if (t == 0) g_is64 = (nz == 0) ? 1 : 0;
}

// ---------------- prepM: M = W2 @ a2 ----------------
__global__ __launch_bounds__(512) void prepM_kernel(const float* __restrict__ W2,
                                                    const float* __restrict__ a_s2,
                                                    const float* __restrict__ a_d2){
    int t = threadIdx.x;
    int k = blockIdx.x;   // 0..63
    __shared__ float sm[16][4];
    float w1  = W2[k*1024 + t];
    float w2v = W2[k*1024 + 512 + t];
    float p1s = w1  * a_s2[t];
    float p1d = w1  * a_d2[t];
    float p2s = w2v * a_s2[512 + t];
    float p2d = w2v * a_d2[512 + t];
#pragma unroll
    for (int off = 16; off; off >>= 1){
        p1s += __shfl_down_sync(~0u, p1s, off);
        p1d += __shfl_down_sync(~0u, p1d, off);
        p2s += __shfl_down_sync(~0u, p2s, off);
        p2d += __shfl_down_sync(~0u, p2d, off);
    }
    int w = t >> 5, l = t & 31;
    if (l == 0){ sm[w][0]=p1s; sm[w][1]=p1d; sm[w][2]=p2s; sm[w][3]=p2d; }
    __syncthreads();
    if (t < 8){
        float ms, md;
        if (t < 4){
            int b = t*4;
            ms = sm[b][0]+sm[b+1][0]+sm[b+2][0]+sm[b+3][0];
            md = sm[b][1]+sm[b+1][1]+sm[b+2][1]+sm[b+3][1];
        } else {
            int b = (t-4)*4;
            ms = sm[b][2]+sm[b+1][2]+sm[b+2][2]+sm[b+3][2];
            md = sm[b][3]+sm[b+1][3]+sm[b+2][3]+sm[b+3][3];
        }
        g_Ms[k*8 + t] = ms;
        g_Md[k*8 + t] = md;
    }
}

// ---------------- CSR build ----------------
__global__ void count_kernel(const void* edge){
    int e = blockIdx.x*256 + threadIdx.x;
    if (e >= NEDGES) return;
    int d;
    if (g_is64) d = (int)((const long long*)edge)[NEDGES + e];
    else        d = ((const int*)edge)[NEDGES + e];
    atomicAdd(&g_deg[d], 1);
}

__global__ __launch_bounds__(1024) void scan_kernel(){
    int t = threadIdx.x, lane = t & 31, w = t >> 5;
    int loc[8]; int s = 0;
#pragma unroll
    for (int j = 0; j < 8; j++){ loc[j] = s; s += g_deg[t*8 + j]; }
    int v = s;
#pragma unroll
    for (int off = 1; off < 32; off <<= 1){
        int n = __shfl_up_sync(~0u, v, off);
        if (lane >= off) v += n;
    }
    __shared__ int wsum[32];
    if (lane == 31) wsum[w] = v;
    __syncthreads();
    if (t < 32){
        int x2 = wsum[t];
#pragma unroll
        for (int off = 1; off < 32; off <<= 1){
            int n = __shfl_up_sync(~0u, x2, off);
            if (t >= off) x2 += n;
        }
        wsum[t] = x2;
    }
    __syncthreads();
    int base = v - s + (w ? wsum[w-1] : 0);
#pragma unroll
    for (int j = 0; j < 8; j++){
        int r = base + loc[j];
        g_rowptr[t*8 + j] = r;
        g_cursor[t*8 + j] = r;
    }
    if (t == 1023) g_rowptr[NNODES] = wsum[31];
}

__global__ void scatter_kernel(const void* edge){
    int e = blockIdx.x*256 + threadIdx.x;
    if (e >= NEDGES) return;
    int s, d;
    if (g_is64){
        s = (int)((const long long*)edge)[e];
        d = (int)((const long long*)edge)[NEDGES + e];
    } else {
        s = ((const int*)edge)[e];
        d = ((const int*)edge)[NEDGES + e];
    }
    int pos = atomicAdd(&g_cursor[d], 1);
    g_srcs[pos] = s;
}

// ---------------- layer 1 linear + attention logits (4 nodes / block) ------
__global__ __launch_bounds__(256) void lin1_kernel(const float* __restrict__ x,
                                                   const float* __restrict__ W1,
                                                   const float* __restrict__ a_s,
                                                   const float* __restrict__ a_d){
    __shared__ float Ws[16*64];
    __shared__ float xs[4][16];
    int t = threadIdx.x;
    int nl = t >> 6, tc = t & 63;
    int n = blockIdx.x*4 + nl;
    for (int i = t; i < 1024; i += 256) Ws[i] = W1[i];
    if (t < 64) xs[t >> 4][t & 15] = x[blockIdx.x*64 + t];
    __syncthreads();
    float acc = 0.f;
#pragma unroll
    for (int k = 0; k < 16; k++) acc += xs[nl][k] * Ws[k*64 + tc];
    g_h1lin[n*64 + tc] = acc;
    float ps = acc * a_s[tc];
    float pd = acc * a_d[tc];
#pragma unroll
    for (int off = 4; off; off >>= 1){
        ps += __shfl_down_sync(~0u, ps, off);
        pd += __shfl_down_sync(~0u, pd, off);
    }
    if ((tc & 7) == 0){
        g_as1[n*8 + (tc>>3)] = ps;
        g_ad1[n*8 + (tc>>3)] = pd;
    }
}

// ---------------- GAT1 aggregation (single-pass, no max) + alpha2 epilogue --
__global__ __launch_bounds__(64) void agg1_kernel(const float* __restrict__ bias){
    int d = blockIdx.x, t = threadIdx.x;
    int g = t >> 3, l8 = t & 7, l32 = t & 31, wid = t >> 5;
    __shared__ float adl[8], den_s[8];
    __shared__ float prS[2][8], prD[2][8];
    if (t < 8) adl[t] = g_ad1[d*8 + t];
    __syncthreads();
    int beg = g_rowptr[d], end = g_rowptr[d+1];
    float ad = adl[g];
    float ws0 = __expf(lrelu(g_as1[d*8 + g] + ad));     // self loop
    float acc = ws0 * g_h1lin[d*64 + t];
    float dp = ws0;
    int i = beg;
    for (; i + 4 <= end; i += 4){
        int s0 = g_srcs[i], s1 = g_srcs[i+1], s2 = g_srcs[i+2], s3 = g_srcs[i+3];
        float w0 = __expf(lrelu(g_as1[s0*8 + g] + ad));
        float w1 = __expf(lrelu(g_as1[s1*8 + g] + ad));
        float w2 = __expf(lrelu(g_as1[s2*8 + g] + ad));
        float w3 = __expf(lrelu(g_as1[s3*8 + g] + ad));
        float v0 = g_h1lin[s0*64 + t];
        float v1 = g_h1lin[s1*64 + t];
        float v2 = g_h1lin[s2*64 + t];
        float v3 = g_h1lin[s3*64 + t];
        dp += w0 + w1 + w2 + w3;
        acc += w0*v0; acc += w1*v1; acc += w2*v2; acc += w3*v3;
    }
    for (; i < end; i++){
        int s = g_srcs[i];
        float we = __expf(lrelu(g_as1[s*8 + g] + ad));
        dp += we;
        acc += we * g_h1lin[s*64 + t];
    }
    if (l8 == 0) den_s[g] = dp + 1e-16f;
    __syncthreads();
    float h1v = fmaxf(acc / den_s[g] + bias[t], 0.f);
    g_h1[d*64 + t] = h1v;
    // fused alpha2: as2[d,h] = h1[d,:] . Ms[:,h]
#pragma unroll
    for (int h = 0; h < 8; h++){
        float vs = h1v * g_Ms[t*8 + h];
        float vd = h1v * g_Md[t*8 + h];
#pragma unroll
        for (int off = 16; off; off >>= 1){
            vs += __shfl_down_sync(~0u, vs, off);
            vd += __shfl_down_sync(~0u, vd, off);
        }
        if (l32 == 0){ prS[wid][h] = vs; prD[wid][h] = vd; }
    }
    __syncthreads();
    if (t < 8){
        g_as2[d*8 + t] = prS[0][t] + prS[1][t];
        g_ad2[d*8 + t] = prD[0][t] + prD[1][t];
    }
}

// ---------------- layer 2 GEMM: h1[8192,64] @ W2[64,1024] -> fp16 ---------
__global__ __launch_bounds__(256) void gemm2_kernel(const float* __restrict__ W2){
    __shared__ float As[64][68];   // [k][m] (transposed)
    __shared__ float Bs[64][68];   // [k][n]
    int t = threadIdx.x;
    int n0 = blockIdx.x*64, m0 = blockIdx.y*64;
#pragma unroll
    for (int q = 0; q < 4; q++){
        int fid = q*256 + t;
        int row = fid >> 4, c4 = fid & 15;
        float4 a = *(const float4*)(g_h1 + (m0+row)*64 + c4*4);
        As[c4*4+0][row] = a.x; As[c4*4+1][row] = a.y;
        As[c4*4+2][row] = a.z; As[c4*4+3][row] = a.w;
        *(float4*)(&Bs[row][c4*4]) = *(const float4*)(W2 + row*1024 + n0 + c4*4);
    }
    __syncthreads();
    int tx = t & 15, ty = t >> 4;
    ull acc[4][2];
#pragma unroll
    for (int i = 0; i < 4; i++){ acc[i][0] = 0ull; acc[i][1] = 0ull; }
#pragma unroll
    for (int k = 0; k < 64; k++){
        float4 a4 = *(const float4*)&As[k][ty*4];
        ull b01 = *(const ull*)&Bs[k][tx*4];
        ull b23 = *(const ull*)&Bs[k][tx*4 + 2];
        ull a0 = pack2(a4.x, a4.x), a1 = pack2(a4.y, a4.y);
        ull a2 = pack2(a4.z, a4.z), a3 = pack2(a4.w, a4.w);
        fma2(acc[0][0], a0, b01); fma2(acc[0][1], a0, b23);
        fma2(acc[1][0], a1, b01); fma2(acc[1][1], a1, b23);
        fma2(acc[2][0], a2, b01); fma2(acc[2][1], a2, b23);
        fma2(acc[3][0], a3, b01); fma2(acc[3][1], a3, b23);
    }
#pragma unroll
    for (int i = 0; i < 4; i++){
        float4 o;
        unpack2(acc[i][0], o.x, o.y);
        unpack2(acc[i][1], o.z, o.w);
        h4 hh;
        hh.a = __floats2half2_rn(o.x, o.y);
        hh.b = __floats2half2_rn(o.z, o.w);
        *(h4*)(g_h2lin_h + (size_t)(m0 + ty*4 + i)*1024 + n0 + tx*4) = hh;
    }
}

// ---------------- GAT2 aggregation (split: 2 blocks per node) --------------
__global__ __launch_bounds__(128) void agg2_kernel(const float* __restrict__ bias){
    int blk = blockIdx.x;
    int d = blk >> 1, half = blk & 1;
    int t = threadIdx.x;
    int w = t >> 5, l = t & 31;
    int head = 4*half + w;
    __shared__ float adl[4], den_s[4];
    if (t < 4) adl[t] = g_ad2[d*8 + 4*half + t];
    __syncthreads();
    int beg = g_rowptr[d], end = g_rowptr[d+1];
    float ad = adl[w];
    float ws0 = __expf(lrelu(g_as2[d*8 + head] + ad));  // self loop
    int cofs = half*512 + t*4;
    float4 acc;
    {
        h4 v = *(const h4*)(g_h2lin_h + (size_t)d*1024 + cofs);
        float2 f0 = __half22float2(v.a), f1 = __half22float2(v.b);
        acc.x = ws0*f0.x; acc.y = ws0*f0.y; acc.z = ws0*f1.x; acc.w = ws0*f1.y;
    }
    float dp = ws0;
    int i = beg;
    for (; i + 4 <= end; i += 4){
        int s0 = g_srcs[i], s1 = g_srcs[i+1], s2 = g_srcs[i+2], s3 = g_srcs[i+3];
        float w0 = __expf(lrelu(g_as2[s0*8 + head] + ad));
        float w1 = __expf(lrelu(g_as2[s1*8 + head] + ad));
        float w2 = __expf(lrelu(g_as2[s2*8 + head] + ad));
        float w3 = __expf(lrelu(g_as2[s3*8 + head] + ad));
        h4 p0 = *(const h4*)(g_h2lin_h + (size_t)s0*1024 + cofs);
        h4 p1 = *(const h4*)(g_h2lin_h + (size_t)s1*1024 + cofs);
        h4 p2 = *(const h4*)(g_h2lin_h + (size_t)s2*1024 + cofs);
        h4 p3 = *(const h4*)(g_h2lin_h + (size_t)s3*1024 + cofs);
        dp += w0 + w1 + w2 + w3;
        float2 a0 = __half22float2(p0.a), b0 = __half22float2(p0.b);
        float2 a1 = __half22float2(p1.a), b1 = __half22float2(p1.b);
        float2 a2 = __half22float2(p2.a), b2 = __half22float2(p2.b);
        float2 a3 = __half22float2(p3.a), b3 = __half22float2(p3.b);
        acc.x += w0*a0.x; acc.y += w0*a0.y; acc.z += w0*b0.x; acc.w += w0*b0.y;
        acc.x += w1*a1.x; acc.y += w1*a1.y; acc.z += w1*b1.x; acc.w += w1*b1.y;
        acc.x += w2*a2.x; acc.y += w2*a2.y; acc.z += w2*b2.x; acc.w += w2*b2.y;
        acc.x += w3*a3.x; acc.y += w3*a3.y; acc.z += w3*b3.x; acc.w += w3*b3.y;
    }
    for (; i < end; i++){
        int s = g_srcs[i];
        float we = __expf(lrelu(g_as2[s*8 + head] + ad));
        h4 p = *(const h4*)(g_h2lin_h + (size_t)s*1024 + cofs);
        float2 a0 = __half22float2(p.a), b0 = __half22float2(p.b);
        dp += we;
        acc.x += we*a0.x; acc.y += we*a0.y; acc.z += we*b0.x; acc.w += we*b0.y;
    }
    if (l == 0) den_s[w] = dp + 1e-16f;
    __syncthreads();
    float inv = 1.f / den_s[w];
    float4 b4 = *(const float4*)(bias + cofs);
    h4 o;
    o.a = __floats2half2_rn(fmaxf(acc.x*inv + b4.x, 0.f), fmaxf(acc.y*inv + b4.y, 0.f));
    o.b = __floats2half2_rn(fmaxf(acc.z*inv + b4.z, 0.f), fmaxf(acc.w*inv + b4.w, 0.f));
    *(h4*)(g_h2h + (size_t)d*1024 + cofs) = o;
}

// ---------------- merged dueling heads GEMV (val 64 cols + adv 16 cols) ----
#define HK_SPAN 1024
#define HK_SUB  256
__global__ __launch_bounds__(256) void head_kernel(const float* __restrict__ Wval,
                                                   const float* __restrict__ Wadv){
    __shared__ __align__(16) float Hs[2][HK_SUB][8];   // 16KB, [buf][k][batch]
    int t = threadIdx.x;
    int w = t >> 5, l = t & 31;
    int kbase = blockIdx.x * HK_SPAN;
    int c4v = t & 15, jv = t >> 4;
    int c4a = t & 3,  ja = t >> 2;
    const float4* Wv4 = (const float4*)Wval;
    const float4* Wa4 = (const float4*)Wadv;

    ull vacc[4][4];                 // [batch-pair][col]
#pragma unroll
    for (int p = 0; p < 4; p++)
#pragma unroll
        for (int c = 0; c < 4; c++) vacc[p][c] = 0ull;
    float4 aa[8];
#pragma unroll
    for (int b = 0; b < 8; b++) aa[b] = make_float4(0.f,0.f,0.f,0.f);

    // preload tile 0 (transposed: Hs[k][b])
#pragma unroll
    for (int q = 0; q < 8; q++)
        Hs[0][t][q] = __half2float(g_h2h[(size_t)q*1048576 + kbase + t]);
    __syncthreads();

    for (int st = 0; st < HK_SPAN/HK_SUB; st++){
        int cur = st & 1;
        float rn[8];
        if (st < HK_SPAN/HK_SUB - 1){
#pragma unroll
            for (int q = 0; q < 8; q++)
                rn[q] = __half2float(g_h2h[(size_t)q*1048576 + kbase + (st+1)*HK_SUB + t]);
        }
        int k0g = kbase + st*HK_SUB;
        // ---- val: 64 cols, f32x2 over batch pairs ----
#pragma unroll 4
        for (int ii = 0; ii < HK_SUB/16; ii++){
            int k = jv + 16*ii;
            float4 w4 = __ldcs(&Wv4[(size_t)(k0g + k)*16 + c4v]);
            ull h01 = *(const ull*)&Hs[cur][k][0];
            ull h23 = *(const ull*)&Hs[cur][k][2];
            ull h45 = *(const ull*)&Hs[cur][k][4];
            ull h67 = *(const ull*)&Hs[cur][k][6];
            ull wx = pack2(w4.x, w4.x), wy = pack2(w4.y, w4.y);
            ull wz = pack2(w4.z, w4.z), ww = pack2(w4.w, w4.w);
            fma2(vacc[0][0], h01, wx); fma2(vacc[1][0], h23, wx);
            fma2(vacc[2][0], h45, wx); fma2(vacc[3][0], h67, wx);
            fma2(vacc[0][1], h01, wy); fma2(vacc[1][1], h23, wy);
            fma2(vacc[2][1], h45, wy); fma2(vacc[3][1], h67, wy);
            fma2(vacc[0][2], h01, wz); fma2(vacc[1][2], h23, wz);
            fma2(vacc[2][2], h45, wz); fma2(vacc[3][2], h67, wz);
            fma2(vacc[0][3], h01, ww); fma2(vacc[1][3], h23, ww);
            fma2(vacc[2][3], h45, ww); fma2(vacc[3][3], h67, ww);
        }
        // ---- adv: 16 cols ----
#pragma unroll
        for (int ii = 0; ii < HK_SUB/64; ii++){
            int k = ja + 64*ii;
            float4 w4 = __ldcs(&Wa4[(size_t)(k0g + k)*4 + c4a]);
#pragma unroll
            for (int b = 0; b < 8; b++){
                float h = Hs[cur][k][b];
                aa[b].x += h*w4.x; aa[b].y += h*w4.y;
                aa[b].z += h*w4.z; aa[b].w += h*w4.w;
            }
        }
        __syncthreads();
        if (st < HK_SPAN/HK_SUB - 1){
#pragma unroll
            for (int q = 0; q < 8; q++) Hs[1-cur][t][q] = rn[q];
            __syncthreads();
        }
    }

    // unpack val accumulators into per-batch float4
    float4 va[8];
#pragma unroll
    for (int p = 0; p < 4; p++){
        float lo, hi;
        unpack2(vacc[p][0], lo, hi); va[2*p].x = lo; va[2*p+1].x = hi;
        unpack2(vacc[p][1], lo, hi); va[2*p].y = lo; va[2*p+1].y = hi;
        unpack2(vacc[p][2], lo, hi); va[2*p].z = lo; va[2*p+1].z = hi;
        unpack2(vacc[p][3], lo, hi); va[2*p].w = lo; va[2*p+1].w = hi;
    }

    float4* red4 = (float4*)&Hs[0][0][0];   // reuse (all threads past final barrier)
    // ---- val reduce: jv pairs (lane offset 16), then across warps ----
#pragma unroll
    for (int b = 0; b < 8; b++) shfl_add(va[b], 16);
    if (l < 16){
#pragma unroll
        for (int b = 0; b < 8; b++) red4[(w*16 + l)*8 + b] = va[b];
    }
    __syncthreads();
    if (t < 128){
        int cc = t & 15, b = t >> 4;
        float4 s = make_float4(0.f,0.f,0.f,0.f);
#pragma unroll
        for (int ww = 0; ww < 8; ww++){
            float4 v = red4[(ww*16 + cc)*8 + b];
            s.x += v.x; s.y += v.y; s.z += v.z; s.w += v.w;
        }
        float* dst = g_valacc + b*64 + cc*4;
        atomicAdd(dst+0, s.x); atomicAdd(dst+1, s.y);
        atomicAdd(dst+2, s.z); atomicAdd(dst+3, s.w);
    }
    __syncthreads();
    // ---- adv reduce: within warp across ja (4,8,16), then warps ----
#pragma unroll
    for (int b = 0; b < 8; b++){
        shfl_add(aa[b], 4); shfl_add(aa[b], 8); shfl_add(aa[b], 16);
    }
    if (l < 4){
#pragma unroll
        for (int b = 0; b < 8; b++) red4[(w*4 + l)*8 + b] = aa[b];
    }
    __syncthreads();
    if (t < 32){
        int cc = t & 3, b = t >> 2;
        float4 s = make_float4(0.f,0.f,0.f,0.f);
#pragma unroll
        for (int ww = 0; ww < 8; ww++){
            float4 v = red4[(ww*4 + cc)*8 + b];
            s.x += v.x; s.y += v.y; s.z += v.z; s.w += v.w;
        }
        float* dst = g_advacc + b*16 + cc*4;
        atomicAdd(dst+0, s.x); atomicAdd(dst+1, s.y);
        atomicAdd(dst+2, s.z); atomicAdd(dst+3, s.w);
    }
}

// ---------------- finalize: val MLP + dueling combine ----------------
__global__ __launch_bounds__(512) void final_kernel(const float* __restrict__ adv_b,
                                                    const float* __restrict__ v1b,
                                                    const float* __restrict__ v2w,
                                                    const float* __restrict__ v2b,
                                                    const float* __restrict__ v3w,
                                                    const float* __restrict__ v3b,
                                                    float* __restrict__ out){
    int t = threadIdx.x;
    __shared__ float v1[512], v2s[512], vS[8], advs[128];
    v1[t] = fmaxf(g_valacc[t] + v1b[t & 63], 0.f);
    if (t < 128) advs[t] = fmaxf(g_advacc[t] + adv_b[t & 15], 0.f);
    __syncthreads();
    {
        int b = t >> 6, c = t & 63;
        float s2 = v2b[c];
        for (int k = 0; k < 64; k++) s2 += v1[b*64 + k] * v2w[k*64 + c];
        v2s[t] = fmaxf(s2, 0.f);
    }
    __syncthreads();
    if (t < 8){
        float s3 = v3b[0];
        for (int k = 0; k < 64; k++) s3 += v2s[t*64 + k] * v3w[k];
        vS[t] = s3;
    }
    __syncthreads();
    if (t < 128){
        int base = t & ~3;
        float mean = 0.25f*(advs[base] + advs[base+1] + advs[base+2] + advs[base+3]);
        out[t] = vS[t >> 4] + advs[t] - mean;
    }
}

// ---------------- launch ----------------
extern "C" void kernel_launch(void* const* d_in, const int* in_sizes, int n_in,
                              void* d_out, int out_size){
    const float* x      = (const float*)d_in[0];
    const void*  edge   = d_in[1];
    const float* W1     = (const float*)d_in[2];
    const float* a_src1 = (const float*)d_in[3];
    const float* a_dst1 = (const float*)d_in[4];
    const float* b1     = (const float*)d_in[5];
    const float* W2     = (const float*)d_in[6];
    const float* a_src2 = (const float*)d_in[7];
    const float* a_dst2 = (const float*)d_in[8];
    const float* b2     = (const float*)d_in[9];
    const float* adv_w  = (const float*)d_in[10];
    const float* adv_b  = (const float*)d_in[11];
    const float* val1_w = (const float*)d_in[12];
    const float* val1_b = (const float*)d_in[13];
    const float* val2_w = (const float*)d_in[14];
    const float* val2_b = (const float*)d_in[15];
    const float* val3_w = (const float*)d_in[16];
    const float* val3_b = (const float*)d_in[17];
    float* out = (float*)d_out;

    static cudaStream_t s1 = nullptr;
    static cudaEvent_t evF = nullptr, evJ = nullptr;
    if (s1 == nullptr){
        cudaStreamCreateWithFlags(&s1, cudaStreamNonBlocking);
        cudaEventCreateWithFlags(&evF, cudaEventDisableTiming);
        cudaEventCreateWithFlags(&evJ, cudaEventDisableTiming);
    }

    // fork: branch stream runs prepM + lin1 while main stream builds CSR
    cudaEventRecord(evF, 0);
    cudaStreamWaitEvent(s1, evF, 0);

    prepM_kernel<<<64, 512, 0, s1>>>(W2, a_src2, a_dst2);
    lin1_kernel<<<NNODES/4, 256, 0, s1>>>(x, W1, a_src1, a_dst1);
    cudaEventRecord(evJ, s1);

    prep0_kernel<<<1, 512>>>((const int*)edge);
    count_kernel<<<NEDGES/256, 256>>>(edge);
    scan_kernel<<<1, 1024>>>();
    scatter_kernel<<<NEDGES/256, 256>>>(edge);

    cudaStreamWaitEvent(0, evJ, 0);   // join before agg1

    agg1_kernel<<<NNODES, 64>>>(b1);
    gemm2_kernel<<<dim3(16, 128), 256>>>(W2);
    agg2_kernel<<<2*NNODES, 128>>>(b2);

    head_kernel<<<1024, 256>>>(val1_w, adv_w);
    final_kernel<<<1, 512>>>(adv_b, val1_b, val2_w, val2_b, val3_w, val3_b, out);
}

// round 10
// speedup vs baseline: 1.0055x; 1.0055x over previous
#include <cuda_runtime.h>
#include <cuda_fp16.h>
#include <cstddef>

#define HEADS  8
#define NNODES 8192
#define NEDGES 131072
#define NEG    0.2f

typedef unsigned long long ull;

// ---------------- scratch (static __device__, no allocation) ----------------
__device__ float  g_h1lin[NNODES*64];
__device__ float  g_as1[NNODES*HEADS];
__device__ float  g_ad1[NNODES*HEADS];
__device__ float  g_h1[NNODES*64];
__device__ __half g_h2lin_h[(size_t)NNODES*1024];  // 16MB fp16 interchange
__device__ __half g_h2h[(size_t)NNODES*1024];      // 16MB fp16 interchange
__device__ float  g_as2[NNODES*HEADS];
__device__ float  g_ad2[NNODES*HEADS];
__device__ int    g_deg[NNODES];
__device__ int    g_rowptr[NNODES+1];
__device__ int    g_cursor[NNODES];
__device__ int    g_srcs[NEDGES];
__device__ int    g_is64;
__device__ float  g_Ms[64*8];
__device__ float  g_Md[64*8];
__device__ float  g_valacc[512];
__device__ float  g_advacc[128];

struct h4 { __half2 a, b; };

__device__ __forceinline__ float lrelu(float x){ return x > 0.f ? x : NEG*x; }

__device__ __forceinline__ void shfl_add(float4& v, int off){
    v.x += __shfl_down_sync(~0u, v.x, off);
    v.y += __shfl_down_sync(~0u, v.y, off);
    v.z += __shfl_down_sync(~0u, v.z, off);
    v.w += __shfl_down_sync(~0u, v.w, off);
}

// ---- packed fp32x2 helpers (Blackwell) ----
__device__ __forceinline__ ull pack2(float lo, float hi){
    ull r;
    asm("mov.b64 %0, {%1, %2};" : "=l"(r) : "r"(__float_as_uint(lo)), "r"(__float_as_uint(hi)));
    return r;
}
__device__ __forceinline__ void unpack2(ull v, float& lo, float& hi){
    unsigned int a, b;
    asm("mov.b64 {%0, %1}, %2;" : "=r"(a), "=r"(b) : "l"(v));
    lo = __uint_as_float(a); hi = __uint_as_float(b);
}
__device__ __forceinline__ void fma2(ull& d, ull a, ull b){
    asm("fma.rn.f32x2 %0, %1, %2, %0;" : "+l"(d) : "l"(a), "l"(b));
}

// ---------------- prep: dtype sniff + zeroing + M = W2 @ a2 ----------------
__global__ __launch_bounds__(512) void prep_kernel(const int* __restrict__ e32,
                                                   const float* __restrict__ W2,
                                                   const float* __restrict__ a_s2,
                                                   const float* __restrict__ a_d2){
    int t = threadIdx.x;
    if (blockIdx.x == 0){
        __shared__ int nz;
        if (t == 0) nz = 0;
        __syncthreads();
        int v = 0;
        for (int i = t; i < 8192; i += 512) v |= e32[2*i+1];
        if (v) atomicOr(&nz, 1);
        for (int i = t; i < NNODES; i += 512) g_deg[i] = 0;
        g_valacc[t] = 0.f;
        if (t < 128) g_advacc[t] = 0.f;
        __syncthreads();
        if (t == 0) g_is64 = (nz == 0) ? 1 : 0;
    } else {
        int k = blockIdx.x - 1;   // 0..63
        __shared__ float sm[16][4];
        float w1  = W2[k*1024 + t];
        float w2v = W2[k*1024 + 512 + t];
        float p1s = w1  * a_s2[t];
        float p1d = w1  * a_d2[t];
        float p2s = w2v * a_s2[512 + t];
        float p2d = w2v * a_d2[512 + t];
#pragma unroll
        for (int off = 16; off; off >>= 1){
            p1s += __shfl_down_sync(~0u, p1s, off);
            p1d += __shfl_down_sync(~0u, p1d, off);
            p2s += __shfl_down_sync(~0u, p2s, off);
            p2d += __shfl_down_sync(~0u, p2d, off);
        }
        int w = t >> 5, l = t & 31;
        if (l == 0){ sm[w][0]=p1s; sm[w][1]=p1d; sm[w][2]=p2s; sm[w][3]=p2d; }
        __syncthreads();
        if (t < 8){
            float ms, md;
            if (t < 4){
                int b = t*4;
                ms = sm[b][0]+sm[b+1][0]+sm[b+2][0]+sm[b+3][0];
                md = sm[b][1]+sm[b+1][1]+sm[b+2][1]+sm[b+3][1];
            } else {
                int b = (t-4)*4;
                ms = sm[b][2]+sm[b+1][2]+sm[b+2][2]+sm[b+3][2];
                md = sm[b][3]+sm[b+1][3]+sm[b+2][3]+sm[b+3][3];
            }
            g_Ms[k*8 + t] = ms;
            g_Md[k*8 + t] = md;
        }
    }
}

// ---------------- CSR build ----------------
__global__ void count_kernel(const void* edge){
    int e = blockIdx.x*256 + threadIdx.x;
    if (e >= NEDGES) return;
    int d;
    if (g_is64) d = (int)((const long long*)edge)[NEDGES + e];
    else        d = ((const int*)edge)[NEDGES + e];
    atomicAdd(&g_deg[d], 1);
}

__global__ __launch_bounds__(1024) void scan_kernel(){
    int t = threadIdx.x, lane = t & 31, w = t >> 5;
    int loc[8]; int s = 0;
#pragma unroll
    for (int j = 0; j < 8; j++){ loc[j] = s; s += g_deg[t*8 + j]; }
    int v = s;
#pragma unroll
    for (int off = 1; off < 32; off <<= 1){
        int n = __shfl_up_sync(~0u, v, off);
        if (lane >= off) v += n;
    }
    __shared__ int wsum[32];
    if (lane == 31) wsum[w] = v;
    __syncthreads();
    if (t < 32){
        int x2 = wsum[t];
#pragma unroll
        for (int off = 1; off < 32; off <<= 1){
            int n = __shfl_up_sync(~0u, x2, off);
            if (t >= off) x2 += n;
        }
        wsum[t] = x2;
    }
    __syncthreads();
    int base = v - s + (w ? wsum[w-1] : 0);
#pragma unroll
    for (int j = 0; j < 8; j++){
        int r = base + loc[j];
        g_rowptr[t*8 + j] = r;
        g_cursor[t*8 + j] = r;
    }
    if (t == 1023) g_rowptr[NNODES] = wsum[31];
}

__global__ void scatter_kernel(const void* edge){
    int e = blockIdx.x*256 + threadIdx.x;
    if (e >= NEDGES) return;
    int s, d;
    if (g_is64){
        s = (int)((const long long*)edge)[e];
        d = (int)((const long long*)edge)[NEDGES + e];
    } else {
        s = ((const int*)edge)[e];
        d = ((const int*)edge)[NEDGES + e];
    }
    int pos = atomicAdd(&g_cursor[d], 1);
    g_srcs[pos] = s;
}

// ---------------- layer 1 linear + attention logits (4 nodes / block) ------
__global__ __launch_bounds__(256) void lin1_kernel(const float* __restrict__ x,
                                                   const float* __restrict__ W1,
                                                   const float* __restrict__ a_s,
                                                   const float* __restrict__ a_d){
    __shared__ float Ws[16*64];
    __shared__ float xs[4][16];
    int t = threadIdx.x;
    int nl = t >> 6, tc = t & 63;
    int n = blockIdx.x*4 + nl;
    for (int i = t; i < 1024; i += 256) Ws[i] = W1[i];
    if (t < 64) xs[t >> 4][t & 15] = x[blockIdx.x*64 + t];
    __syncthreads();
    float acc = 0.f;
#pragma unroll
    for (int k = 0; k < 16; k++) acc += xs[nl][k] * Ws[k*64 + tc];
    g_h1lin[n*64 + tc] = acc;
    float ps = acc * a_s[tc];
    float pd = acc * a_d[tc];
#pragma unroll
    for (int off = 4; off; off >>= 1){
        ps += __shfl_down_sync(~0u, ps, off);
        pd += __shfl_down_sync(~0u, pd, off);
    }
    if ((tc & 7) == 0){
        g_as1[n*8 + (tc>>3)] = ps;
        g_ad1[n*8 + (tc>>3)] = pd;
    }
}

// ---------------- GAT1 aggregation (single-pass, unroll 8) + alpha2 --------
__global__ __launch_bounds__(64) void agg1_kernel(const float* __restrict__ bias){
    int d = blockIdx.x, t = threadIdx.x;
    int g = t >> 3, l8 = t & 7, l32 = t & 31, wid = t >> 5;
    __shared__ float adl[8], den_s[8];
    __shared__ float prS[2][8], prD[2][8];
    if (t < 8) adl[t] = g_ad1[d*8 + t];
    __syncthreads();
    int beg = g_rowptr[d], end = g_rowptr[d+1];
    float ad = adl[g];
    float ws0 = __expf(lrelu(g_as1[d*8 + g] + ad));     // self loop
    float acc = ws0 * g_h1lin[d*64 + t];
    float dp = ws0;
    int i = beg;
    for (; i + 8 <= end; i += 8){
        int sI[8]; float wE[8], vE[8];
#pragma unroll
        for (int q = 0; q < 8; q++) sI[q] = g_srcs[i+q];
#pragma unroll
        for (int q = 0; q < 8; q++) wE[q] = __expf(lrelu(g_as1[sI[q]*8 + g] + ad));
#pragma unroll
        for (int q = 0; q < 8; q++) vE[q] = g_h1lin[sI[q]*64 + t];
#pragma unroll
        for (int q = 0; q < 8; q++){ dp += wE[q]; acc += wE[q]*vE[q]; }
    }
    for (; i < end; i++){
        int s = g_srcs[i];
        float we = __expf(lrelu(g_as1[s*8 + g] + ad));
        dp += we;
        acc += we * g_h1lin[s*64 + t];
    }
    if (l8 == 0) den_s[g] = dp + 1e-16f;
    __syncthreads();
    float h1v = fmaxf(acc / den_s[g] + bias[t], 0.f);
    g_h1[d*64 + t] = h1v;
    // fused alpha2: as2[d,h] = h1[d,:] . Ms[:,h]
#pragma unroll
    for (int h = 0; h < 8; h++){
        float vs = h1v * g_Ms[t*8 + h];
        float vd = h1v * g_Md[t*8 + h];
#pragma unroll
        for (int off = 16; off; off >>= 1){
            vs += __shfl_down_sync(~0u, vs, off);
            vd += __shfl_down_sync(~0u, vd, off);
        }
        if (l32 == 0){ prS[wid][h] = vs; prD[wid][h] = vd; }
    }
    __syncthreads();
    if (t < 8){
        g_as2[d*8 + t] = prS[0][t] + prS[1][t];
        g_ad2[d*8 + t] = prD[0][t] + prD[1][t];
    }
}

// ---------------- layer 2 GEMM: h1[8192,64] @ W2[64,1024] -> fp16 ---------
__global__ __launch_bounds__(256) void gemm2_kernel(const float* __restrict__ W2){
    __shared__ float As[64][68];   // [k][m] (transposed)
    __shared__ float Bs[64][68];   // [k][n]
    int t = threadIdx.x;
    int n0 = blockIdx.x*64, m0 = blockIdx.y*64;
#pragma unroll
    for (int q = 0; q < 4; q++){
        int fid = q*256 + t;
        int row = fid >> 4, c4 = fid & 15;
        float4 a = *(const float4*)(g_h1 + (m0+row)*64 + c4*4);
        As[c4*4+0][row] = a.x; As[c4*4+1][row] = a.y;
        As[c4*4+2][row] = a.z; As[c4*4+3][row] = a.w;
        *(float4*)(&Bs[row][c4*4]) = *(const float4*)(W2 + row*1024 + n0 + c4*4);
    }
    __syncthreads();
    int tx = t & 15, ty = t >> 4;
    ull acc[4][2];
#pragma unroll
    for (int i = 0; i < 4; i++){ acc[i][0] = 0ull; acc[i][1] = 0ull; }
#pragma unroll
    for (int k = 0; k < 64; k++){
        float4 a4 = *(const float4*)&As[k][ty*4];
        ull b01 = *(const ull*)&Bs[k][tx*4];
        ull b23 = *(const ull*)&Bs[k][tx*4 + 2];
        ull a0 = pack2(a4.x, a4.x), a1 = pack2(a4.y, a4.y);
        ull a2 = pack2(a4.z, a4.z), a3 = pack2(a4.w, a4.w);
        fma2(acc[0][0], a0, b01); fma2(acc[0][1], a0, b23);
        fma2(acc[1][0], a1, b01); fma2(acc[1][1], a1, b23);
        fma2(acc[2][0], a2, b01); fma2(acc[2][1], a2, b23);
        fma2(acc[3][0], a3, b01); fma2(acc[3][1], a3, b23);
    }
#pragma unroll
    for (int i = 0; i < 4; i++){
        float4 o;
        unpack2(acc[i][0], o.x, o.y);
        unpack2(acc[i][1], o.z, o.w);
        h4 hh;
        hh.a = __floats2half2_rn(o.x, o.y);
        hh.b = __floats2half2_rn(o.z, o.w);
        *(h4*)(g_h2lin_h + (size_t)(m0 + ty*4 + i)*1024 + n0 + tx*4) = hh;
    }
}

// ---------------- GAT2 aggregation (single-pass, fp16 gather, unroll 8) ----
__global__ __launch_bounds__(256) void agg2_kernel(const float* __restrict__ bias){
    int d = blockIdx.x, t = threadIdx.x;
    int w = t >> 5, l = t & 31;
    __shared__ float adl[8], den_s[8];
    if (t < 8) adl[t] = g_ad2[d*8 + t];
    __syncthreads();
    int beg = g_rowptr[d], end = g_rowptr[d+1];
    float ad = adl[w];
    float ws0 = __expf(lrelu(g_as2[d*8 + w] + ad));     // self loop
    int cofs = t*4;
    float4 acc;
    {
        h4 v = *(const h4*)(g_h2lin_h + (size_t)d*1024 + cofs);
        float2 f0 = __half22float2(v.a), f1 = __half22float2(v.b);
        acc.x = ws0*f0.x; acc.y = ws0*f0.y; acc.z = ws0*f1.x; acc.w = ws0*f1.y;
    }
    float dp = ws0;
    int i = beg;
    for (; i + 8 <= end; i += 8){
        int sI[8]; float wE[8]; h4 pE[8];
#pragma unroll
        for (int q = 0; q < 8; q++) sI[q] = g_srcs[i+q];
#pragma unroll
        for (int q = 0; q < 8; q++) wE[q] = __expf(lrelu(g_as2[sI[q]*8 + w] + ad));
#pragma unroll
        for (int q = 0; q < 8; q++) pE[q] = *(const h4*)(g_h2lin_h + (size_t)sI[q]*1024 + cofs);
#pragma unroll
        for (int q = 0; q < 8; q++){
            float2 a0 = __half22float2(pE[q].a), b0 = __half22float2(pE[q].b);
            dp += wE[q];
            acc.x += wE[q]*a0.x; acc.y += wE[q]*a0.y;
            acc.z += wE[q]*b0.x; acc.w += wE[q]*b0.y;
        }
    }
    for (; i < end; i++){
        int s = g_srcs[i];
        float we = __expf(lrelu(g_as2[s*8 + w] + ad));
        h4 p = *(const h4*)(g_h2lin_h + (size_t)s*1024 + cofs);
        float2 a0 = __half22float2(p.a), b0 = __half22float2(p.b);
        dp += we;
        acc.x += we*a0.x; acc.y += we*a0.y; acc.z += we*b0.x; acc.w += we*b0.y;
    }
    if (l == 0) den_s[w] = dp + 1e-16f;
    __syncthreads();
    float inv = 1.f / den_s[w];
    float4 b4 = *(const float4*)(bias + cofs);
    h4 o;
    o.a = __floats2half2_rn(fmaxf(acc.x*inv + b4.x, 0.f), fmaxf(acc.y*inv + b4.y, 0.f));
    o.b = __floats2half2_rn(fmaxf(acc.z*inv + b4.z, 0.f), fmaxf(acc.w*inv + b4.w, 0.f));
    *(h4*)(g_h2h + (size_t)d*1024 + cofs) = o;
}

// ---------------- merged dueling heads GEMV (val 64 cols + adv 16 cols) ----
#define HK_SPAN 1024
#define HK_SUB  256
__global__ __launch_bounds__(256) void head_kernel(const float* __restrict__ Wval,
                                                   const float* __restrict__ Wadv){
    __shared__ __align__(16) float Hs[2][HK_SUB][8];   // 16KB, [buf][k][batch]
    int t = threadIdx.x;
    int w = t >> 5, l = t & 31;
    int kbase = blockIdx.x * HK_SPAN;
    int c4v = t & 15, jv = t >> 4;
    int c4a = t & 3,  ja = t >> 2;
    const float4* Wv4 = (const float4*)Wval;
    const float4* Wa4 = (const float4*)Wadv;

    ull vacc[4][4];                 // [batch-pair][col]
#pragma unroll
    for (int p = 0; p < 4; p++)
#pragma unroll
        for (int c = 0; c < 4; c++) vacc[p][c] = 0ull;
    float4 aa[8];
#pragma unroll
    for (int b = 0; b < 8; b++) aa[b] = make_float4(0.f,0.f,0.f,0.f);

    // preload tile 0 (transposed: Hs[k][b])
#pragma unroll
    for (int q = 0; q < 8; q++)
        Hs[0][t][q] = __half2float(g_h2h[(size_t)q*1048576 + kbase + t]);
    __syncthreads();

    for (int st = 0; st < HK_SPAN/HK_SUB; st++){
        int cur = st & 1;
        float rn[8];
        if (st < HK_SPAN/HK_SUB - 1){
#pragma unroll
            for (int q = 0; q < 8; q++)
                rn[q] = __half2float(g_h2h[(size_t)q*1048576 + kbase + (st+1)*HK_SUB + t]);
        }
        int k0g = kbase + st*HK_SUB;
        // ---- val: 64 cols, f32x2 over batch pairs ----
#pragma unroll 4
        for (int ii = 0; ii < HK_SUB/16; ii++){
            int k = jv + 16*ii;
            float4 w4 = __ldcs(&Wv4[(size_t)(k0g + k)*16 + c4v]);
            ull h01 = *(const ull*)&Hs[cur][k][0];
            ull h23 = *(const ull*)&Hs[cur][k][2];
            ull h45 = *(const ull*)&Hs[cur][k][4];
            ull h67 = *(const ull*)&Hs[cur][k][6];
            ull wx = pack2(w4.x, w4.x), wy = pack2(w4.y, w4.y);
            ull wz = pack2(w4.z, w4.z), ww = pack2(w4.w, w4.w);
            fma2(vacc[0][0], h01, wx); fma2(vacc[1][0], h23, wx);
            fma2(vacc[2][0], h45, wx); fma2(vacc[3][0], h67, wx);
            fma2(vacc[0][1], h01, wy); fma2(vacc[1][1], h23, wy);
            fma2(vacc[2][1], h45, wy); fma2(vacc[3][1], h67, wy);
            fma2(vacc[0][2], h01, wz); fma2(vacc[1][2], h23, wz);
            fma2(vacc[2][2], h45, wz); fma2(vacc[3][2], h67, wz);
            fma2(vacc[0][3], h01, ww); fma2(vacc[1][3], h23, ww);
            fma2(vacc[2][3], h45, ww); fma2(vacc[3][3], h67, ww);
        }
        // ---- adv: 16 cols ----
#pragma unroll
        for (int ii = 0; ii < HK_SUB/64; ii++){
            int k = ja + 64*ii;
            float4 w4 = __ldcs(&Wa4[(size_t)(k0g + k)*4 + c4a]);
#pragma unroll
            for (int b = 0; b < 8; b++){
                float h = Hs[cur][k][b];
                aa[b].x += h*w4.x; aa[b].y += h*w4.y;
                aa[b].z += h*w4.z; aa[b].w += h*w4.w;
            }
        }
        __syncthreads();
        if (st < HK_SPAN/HK_SUB - 1){
#pragma unroll
            for (int q = 0; q < 8; q++) Hs[1-cur][t][q] = rn[q];
            __syncthreads();
        }
    }

    // unpack val accumulators into per-batch float4
    float4 va[8];
#pragma unroll
    for (int p = 0; p < 4; p++){
        float lo, hi;
        unpack2(vacc[p][0], lo, hi); va[2*p].x = lo; va[2*p+1].x = hi;
        unpack2(vacc[p][1], lo, hi); va[2*p].y = lo; va[2*p+1].y = hi;
        unpack2(vacc[p][2], lo, hi); va[2*p].z = lo; va[2*p+1].z = hi;
        unpack2(vacc[p][3], lo, hi); va[2*p].w = lo; va[2*p+1].w = hi;
    }

    float4* red4 = (float4*)&Hs[0][0][0];   // reuse (all threads past final barrier)
    // ---- val reduce: jv pairs (lane offset 16), then across warps ----
#pragma unroll
    for (int b = 0; b < 8; b++) shfl_add(va[b], 16);
    if (l < 16){
#pragma unroll
        for (int b = 0; b < 8; b++) red4[(w*16 + l)*8 + b] = va[b];
    }
    __syncthreads();
    if (t < 128){
        int cc = t & 15, b = t >> 4;
        float4 s = make_float4(0.f,0.f,0.f,0.f);
#pragma unroll
        for (int ww = 0; ww < 8; ww++){
            float4 v = red4[(ww*16 + cc)*8 + b];
            s.x += v.x; s.y += v.y; s.z += v.z; s.w += v.w;
        }
        float* dst = g_valacc + b*64 + cc*4;
        atomicAdd(dst+0, s.x); atomicAdd(dst+1, s.y);
        atomicAdd(dst+2, s.z); atomicAdd(dst+3, s.w);
    }
    __syncthreads();
    // ---- adv reduce: within warp across ja (4,8,16), then warps ----
#pragma unroll
    for (int b = 0; b < 8; b++){
        shfl_add(aa[b], 4); shfl_add(aa[b], 8); shfl_add(aa[b], 16);
    }
    if (l < 4){
#pragma unroll
        for (int b = 0; b < 8; b++) red4[(w*4 + l)*8 + b] = aa[b];
    }
    __syncthreads();
    if (t < 32){
        int cc = t & 3, b = t >> 2;
        float4 s = make_float4(0.f,0.f,0.f,0.f);
#pragma unroll
        for (int ww = 0; ww < 8; ww++){
            float4 v = red4[(ww*4 + cc)*8 + b];
            s.x += v.x; s.y += v.y; s.z += v.z; s.w += v.w;
        }
        float* dst = g_advacc + b*16 + cc*4;
        atomicAdd(dst+0, s.x); atomicAdd(dst+1, s.y);
        atomicAdd(dst+2, s.z); atomicAdd(dst+3, s.w);
    }
}

// ---------------- finalize: val MLP + dueling combine ----------------
__global__ __launch_bounds__(512) void final_kernel(const float* __restrict__ adv_b,
                                                    const float* __restrict__ v1b,
                                                    const float* __restrict__ v2w,
                                                    const float* __restrict__ v2b,
                                                    const float* __restrict__ v3w,
                                                    const float* __restrict__ v3b,
                                                    float* __restrict__ out){
    int t = threadIdx.x;
    __shared__ float v1[512], v2s[512], vS[8], advs[128];
    v1[t] = fmaxf(g_valacc[t] + v1b[t & 63], 0.f);
    if (t < 128) advs[t] = fmaxf(g_advacc[t] + adv_b[t & 15], 0.f);
    __syncthreads();
    {
        int b = t >> 6, c = t & 63;
        float s2 = v2b[c];
        for (int k = 0; k < 64; k++) s2 += v1[b*64 + k] * v2w[k*64 + c];
        v2s[t] = fmaxf(s2, 0.f);
    }
    __syncthreads();
    if (t < 8){
        float s3 = v3b[0];
        for (int k = 0; k < 64; k++) s3 += v2s[t*64 + k] * v3w[k];
        vS[t] = s3;
    }
    __syncthreads();
    if (t < 128){
        int base = t & ~3;
        float mean = 0.25f*(advs[base] + advs[base+1] + advs[base+2] + advs[base+3]);
        out[t] = vS[t >> 4] + advs[t] - mean;
    }
}

// ---------------- launch ----------------
extern "C" void kernel_launch(void* const* d_in, const int* in_sizes, int n_in,
                              void* d_out, int out_size){
    const float* x      = (const float*)d_in[0];
    const void*  edge   = d_in[1];
    const float* W1     = (const float*)d_in[2];
    const float* a_src1 = (const float*)d_in[3];
    const float* a_dst1 = (const float*)d_in[4];
    const float* b1     = (const float*)d_in[5];
    const float* W2     = (const float*)d_in[6];
    const float* a_src2 = (const float*)d_in[7];
    const float* a_dst2 = (const float*)d_in[8];
    const float* b2     = (const float*)d_in[9];
    const float* adv_w  = (const float*)d_in[10];
    const float* adv_b  = (const float*)d_in[11];
    const float* val1_w = (const float*)d_in[12];
    const float* val1_b = (const float*)d_in[13];
    const float* val2_w = (const float*)d_in[14];
    const float* val2_b = (const float*)d_in[15];
    const float* val3_w = (const float*)d_in[16];
    const float* val3_b = (const float*)d_in[17];
    float* out = (float*)d_out;

    prep_kernel<<<65, 512>>>((const int*)edge, W2, a_src2, a_dst2);
    count_kernel<<<NEDGES/256, 256>>>(edge);
    scan_kernel<<<1, 1024>>>();
    scatter_kernel<<<NEDGES/256, 256>>>(edge);

    lin1_kernel<<<NNODES/4, 256>>>(x, W1, a_src1, a_dst1);
    agg1_kernel<<<NNODES, 64>>>(b1);

    gemm2_kernel<<<dim3(16, 128), 256>>>(W2);
    agg2_kernel<<<NNODES, 256>>>(b2);

    head_kernel<<<1024, 256>>>(val1_w, adv_w);
    final_kernel<<<1, 512>>>(adv_b, val1_b, val2_w, val2_b, val3_w, val3_b, out);
}

// round 11
// speedup vs baseline: 1.0271x; 1.0215x over previous
#include <cuda_runtime.h>
#include <cuda_fp16.h>
#include <cstddef>

#define HEADS  8
#define NNODES 8192
#define NEDGES 131072
#define NEG    0.2f

typedef unsigned long long ull;

// ---------------- scratch (static __device__, no allocation) ----------------
__device__ float  g_h1lin[NNODES*64];
__device__ float  g_as1[NNODES*HEADS];
__device__ float  g_ad1[NNODES*HEADS];
__device__ float  g_h1[NNODES*64];
__device__ __half g_h2lin_h[(size_t)NNODES*1024];  // 16MB fp16 interchange
__device__ __half g_h2h[(size_t)NNODES*1024];      // 16MB fp16 interchange
__device__ float  g_as2[NNODES*HEADS];
__device__ float  g_ad2[NNODES*HEADS];
__device__ int    g_deg[NNODES];
__device__ int    g_rowptr[NNODES+1];
__device__ int    g_cursor[NNODES];
__device__ int    g_srcs[NEDGES];
__device__ int    g_is64;
__device__ float  g_Ms[64*8];
__device__ float  g_Md[64*8];
__device__ float  g_valacc[512];
__device__ float  g_advacc[128];

struct h4 { __half2 a, b; };

__device__ __forceinline__ float lrelu(float x){ return x > 0.f ? x : NEG*x; }

__device__ __forceinline__ void shfl_add(float4& v, int off){
    v.x += __shfl_down_sync(~0u, v.x, off);
    v.y += __shfl_down_sync(~0u, v.y, off);
    v.z += __shfl_down_sync(~0u, v.z, off);
    v.w += __shfl_down_sync(~0u, v.w, off);
}

// ---- packed fp32x2 helpers (Blackwell) ----
__device__ __forceinline__ ull pack2(float lo, float hi){
    ull r;
    asm("mov.b64 %0, {%1, %2};" : "=l"(r) : "r"(__float_as_uint(lo)), "r"(__float_as_uint(hi)));
    return r;
}
__device__ __forceinline__ void unpack2(ull v, float& lo, float& hi){
    unsigned int a, b;
    asm("mov.b64 {%0, %1}, %2;" : "=r"(a), "=r"(b) : "l"(v));
    lo = __uint_as_float(a); hi = __uint_as_float(b);
}
__device__ __forceinline__ void fma2(ull& d, ull a, ull b){
    asm("fma.rn.f32x2 %0, %1, %2, %0;" : "+l"(d) : "l"(a), "l"(b));
}

// ---------------- prep0: dtype sniff + zeroing ----------------
__global__ __launch_bounds__(512) void prep0_kernel(const int* __restrict__ e32){
    int t = threadIdx.x;
    __shared__ int nz;
    if (t == 0) nz = 0;
    __syncthreads();
    int v = 0;
    for (int i = t; i < 8192; i += 512) v |= e32[2*i+1];
    if (v) atomicOr(&nz, 1);
    for (int i = t; i < NNODES; i += 512) g_deg[i] = 0;
    g_valacc[t] = 0.f;
    if (t < 128) g_advacc[t] = 0.f;
    __syncthreads();
    if (t == 0) g_is64 = (nz == 0) ? 1 : 0;
}

// ---------------- prepM: M = W2 @ a2 ----------------
__global__ __launch_bounds__(512) void prepM_kernel(const float* __restrict__ W2,
                                                    const float* __restrict__ a_s2,
                                                    const float* __restrict__ a_d2){
    int t = threadIdx.x;
    int k = blockIdx.x;   // 0..63
    __shared__ float sm[16][4];
    float w1  = W2[k*1024 + t];
    float w2v = W2[k*1024 + 512 + t];
    float p1s = w1  * a_s2[t];
    float p1d = w1  * a_d2[t];
    float p2s = w2v * a_s2[512 + t];
    float p2d = w2v * a_d2[512 + t];
#pragma unroll
    for (int off = 16; off; off >>= 1){
        p1s += __shfl_down_sync(~0u, p1s, off);
        p1d += __shfl_down_sync(~0u, p1d, off);
        p2s += __shfl_down_sync(~0u, p2s, off);
        p2d += __shfl_down_sync(~0u, p2d, off);
    }
    int w = t >> 5, l = t & 31;
    if (l == 0){ sm[w][0]=p1s; sm[w][1]=p1d; sm[w][2]=p2s; sm[w][3]=p2d; }
    __syncthreads();
    if (t < 8){
        float ms, md;
        if (t < 4){
            int b = t*4;
            ms = sm[b][0]+sm[b+1][0]+sm[b+2][0]+sm[b+3][0];
            md = sm[b][1]+sm[b+1][1]+sm[b+2][1]+sm[b+3][1];
        } else {
            int b = (t-4)*4;
            ms = sm[b][2]+sm[b+1][2]+sm[b+2][2]+sm[b+3][2];
            md = sm[b][3]+sm[b+1][3]+sm[b+2][3]+sm[b+3][3];
        }
        g_Ms[k*8 + t] = ms;
        g_Md[k*8 + t] = md;
    }
}

// ---------------- CSR build ----------------
__global__ void count_kernel(const void* edge){
    int e = blockIdx.x*256 + threadIdx.x;
    if (e >= NEDGES) return;
    int d;
    if (g_is64) d = (int)((const long long*)edge)[NEDGES + e];
    else        d = ((const int*)edge)[NEDGES + e];
    atomicAdd(&g_deg[d], 1);
}

__global__ __launch_bounds__(1024) void scan_kernel(){
    int t = threadIdx.x, lane = t & 31, w = t >> 5;
    int loc[8]; int s = 0;
#pragma unroll
    for (int j = 0; j < 8; j++){ loc[j] = s; s += g_deg[t*8 + j]; }
    int v = s;
#pragma unroll
    for (int off = 1; off < 32; off <<= 1){
        int n = __shfl_up_sync(~0u, v, off);
        if (lane >= off) v += n;
    }
    __shared__ int wsum[32];
    if (lane == 31) wsum[w] = v;
    __syncthreads();
    if (t < 32){
        int x2 = wsum[t];
#pragma unroll
        for (int off = 1; off < 32; off <<= 1){
            int n = __shfl_up_sync(~0u, x2, off);
            if (t >= off) x2 += n;
        }
        wsum[t] = x2;
    }
    __syncthreads();
    int base = v - s + (w ? wsum[w-1] : 0);
#pragma unroll
    for (int j = 0; j < 8; j++){
        int r = base + loc[j];
        g_rowptr[t*8 + j] = r;
        g_cursor[t*8 + j] = r;
    }
    if (t == 1023) g_rowptr[NNODES] = wsum[31];
}

__global__ void scatter_kernel(const void* edge){
    int e = blockIdx.x*256 + threadIdx.x;
    if (e >= NEDGES) return;
    int s, d;
    if (g_is64){
        s = (int)((const long long*)edge)[e];
        d = (int)((const long long*)edge)[NEDGES + e];
    } else {
        s = ((const int*)edge)[e];
        d = ((const int*)edge)[NEDGES + e];
    }
    int pos = atomicAdd(&g_cursor[d], 1);
    g_srcs[pos] = s;
}

// ---------------- layer 1 linear + attention logits (4 nodes / block) ------
__global__ __launch_bounds__(256) void lin1_kernel(const float* __restrict__ x,
                                                   const float* __restrict__ W1,
                                                   const float* __restrict__ a_s,
                                                   const float* __restrict__ a_d){
    __shared__ float Ws[16*64];
    __shared__ float xs[4][16];
    int t = threadIdx.x;
    int nl = t >> 6, tc = t & 63;
    int n = blockIdx.x*4 + nl;
    for (int i = t; i < 1024; i += 256) Ws[i] = W1[i];
    if (t < 64) xs[t >> 4][t & 15] = x[blockIdx.x*64 + t];
    __syncthreads();
    float acc = 0.f;
#pragma unroll
    for (int k = 0; k < 16; k++) acc += xs[nl][k] * Ws[k*64 + tc];
    g_h1lin[n*64 + tc] = acc;
    float ps = acc * a_s[tc];
    float pd = acc * a_d[tc];
#pragma unroll
    for (int off = 4; off; off >>= 1){
        ps += __shfl_down_sync(~0u, ps, off);
        pd += __shfl_down_sync(~0u, pd, off);
    }
    if ((tc & 7) == 0){
        g_as1[n*8 + (tc>>3)] = ps;
        g_ad1[n*8 + (tc>>3)] = pd;
    }
}

// ---------------- GAT1 aggregation (single-pass, no max) + alpha2 epilogue --
__global__ __launch_bounds__(64) void agg1_kernel(const float* __restrict__ bias){
    int d = blockIdx.x, t = threadIdx.x;
    int g = t >> 3, l8 = t & 7, l32 = t & 31, wid = t >> 5;
    __shared__ float adl[8], den_s[8];
    __shared__ float prS[2][8], prD[2][8];
    if (t < 8) adl[t] = g_ad1[d*8 + t];
    __syncthreads();
    int beg = g_rowptr[d], end = g_rowptr[d+1];
    float ad = adl[g];
    float ws0 = __expf(lrelu(g_as1[d*8 + g] + ad));     // self loop
    float acc = ws0 * g_h1lin[d*64 + t];
    float dp = ws0;
    int i = beg;
    for (; i + 4 <= end; i += 4){
        int s0 = g_srcs[i], s1 = g_srcs[i+1], s2 = g_srcs[i+2], s3 = g_srcs[i+3];
        float w0 = __expf(lrelu(g_as1[s0*8 + g] + ad));
        float w1 = __expf(lrelu(g_as1[s1*8 + g] + ad));
        float w2 = __expf(lrelu(g_as1[s2*8 + g] + ad));
        float w3 = __expf(lrelu(g_as1[s3*8 + g] + ad));
        float v0 = g_h1lin[s0*64 + t];
        float v1 = g_h1lin[s1*64 + t];
        float v2 = g_h1lin[s2*64 + t];
        float v3 = g_h1lin[s3*64 + t];
        dp += w0 + w1 + w2 + w3;
        acc += w0*v0; acc += w1*v1; acc += w2*v2; acc += w3*v3;
    }
    for (; i < end; i++){
        int s = g_srcs[i];
        float we = __expf(lrelu(g_as1[s*8 + g] + ad));
        dp += we;
        acc += we * g_h1lin[s*64 + t];
    }
    if (l8 == 0) den_s[g] = dp + 1e-16f;
    __syncthreads();
    float h1v = fmaxf(acc / den_s[g] + bias[t], 0.f);
    g_h1[d*64 + t] = h1v;
    // fused alpha2: as2[d,h] = h1[d,:] . Ms[:,h]
#pragma unroll
    for (int h = 0; h < 8; h++){
        float vs = h1v * g_Ms[t*8 + h];
        float vd = h1v * g_Md[t*8 + h];
#pragma unroll
        for (int off = 16; off; off >>= 1){
            vs += __shfl_down_sync(~0u, vs, off);
            vd += __shfl_down_sync(~0u, vd, off);
        }
        if (l32 == 0){ prS[wid][h] = vs; prD[wid][h] = vd; }
    }
    __syncthreads();
    if (t < 8){
        g_as2[d*8 + t] = prS[0][t] + prS[1][t];
        g_ad2[d*8 + t] = prD[0][t] + prD[1][t];
    }
}

// ---------------- layer 2 GEMM: h1[8192,64] @ W2[64,1024] -> fp16 ---------
__global__ __launch_bounds__(256) void gemm2_kernel(const float* __restrict__ W2){
    __shared__ float As[64][68];   // [k][m] (transposed)
    __shared__ float Bs[64][68];   // [k][n]
    int t = threadIdx.x;
    int n0 = blockIdx.x*64, m0 = blockIdx.y*64;
#pragma unroll
    for (int q = 0; q < 4; q++){
        int fid = q*256 + t;
        int row = fid >> 4, c4 = fid & 15;
        float4 a = *(const float4*)(g_h1 + (m0+row)*64 + c4*4);
        As[c4*4+0][row] = a.x; As[c4*4+1][row] = a.y;
        As[c4*4+2][row] = a.z; As[c4*4+3][row] = a.w;
        *(float4*)(&Bs[row][c4*4]) = *(const float4*)(W2 + row*1024 + n0 + c4*4);
    }
    __syncthreads();
    int tx = t & 15, ty = t >> 4;
    ull acc[4][2];
#pragma unroll
    for (int i = 0; i < 4; i++){ acc[i][0] = 0ull; acc[i][1] = 0ull; }
#pragma unroll
    for (int k = 0; k < 64; k++){
        float4 a4 = *(const float4*)&As[k][ty*4];
        ull b01 = *(const ull*)&Bs[k][tx*4];
        ull b23 = *(const ull*)&Bs[k][tx*4 + 2];
        ull a0 = pack2(a4.x, a4.x), a1 = pack2(a4.y, a4.y);
        ull a2 = pack2(a4.z, a4.z), a3 = pack2(a4.w, a4.w);
        fma2(acc[0][0], a0, b01); fma2(acc[0][1], a0, b23);
        fma2(acc[1][0], a1, b01); fma2(acc[1][1], a1, b23);
        fma2(acc[2][0], a2, b01); fma2(acc[2][1], a2, b23);
        fma2(acc[3][0], a3, b01); fma2(acc[3][1], a3, b23);
    }
#pragma unroll
    for (int i = 0; i < 4; i++){
        float4 o;
        unpack2(acc[i][0], o.x, o.y);
        unpack2(acc[i][1], o.z, o.w);
        h4 hh;
        hh.a = __floats2half2_rn(o.x, o.y);
        hh.b = __floats2half2_rn(o.z, o.w);
        *(h4*)(g_h2lin_h + (size_t)(m0 + ty*4 + i)*1024 + n0 + tx*4) = hh;
    }
}

// ---------------- GAT2 aggregation (single-pass, fp16 gather) --------------
__global__ __launch_bounds__(256) void agg2_kernel(const float* __restrict__ bias){
    int d = blockIdx.x, t = threadIdx.x;
    int w = t >> 5, l = t & 31;
    __shared__ float adl[8], den_s[8];
    if (t < 8) adl[t] = g_ad2[d*8 + t];
    __syncthreads();
    int beg = g_rowptr[d], end = g_rowptr[d+1];
    float ad = adl[w];
    float ws0 = __expf(lrelu(g_as2[d*8 + w] + ad));     // self loop
    int cofs = t*4;
    float4 acc;
    {
        h4 v = *(const h4*)(g_h2lin_h + (size_t)d*1024 + cofs);
        float2 f0 = __half22float2(v.a), f1 = __half22float2(v.b);
        acc.x = ws0*f0.x; acc.y = ws0*f0.y; acc.z = ws0*f1.x; acc.w = ws0*f1.y;
    }
    float dp = ws0;
    int i = beg;
    for (; i + 4 <= end; i += 4){
        int s0 = g_srcs[i], s1 = g_srcs[i+1], s2 = g_srcs[i+2], s3 = g_srcs[i+3];
        float w0 = __expf(lrelu(g_as2[s0*8 + w] + ad));
        float w1 = __expf(lrelu(g_as2[s1*8 + w] + ad));
        float w2 = __expf(lrelu(g_as2[s2*8 + w] + ad));
        float w3 = __expf(lrelu(g_as2[s3*8 + w] + ad));
        h4 p0 = *(const h4*)(g_h2lin_h + (size_t)s0*1024 + cofs);
        h4 p1 = *(const h4*)(g_h2lin_h + (size_t)s1*1024 + cofs);
        h4 p2 = *(const h4*)(g_h2lin_h + (size_t)s2*1024 + cofs);
        h4 p3 = *(const h4*)(g_h2lin_h + (size_t)s3*1024 + cofs);
        dp += w0 + w1 + w2 + w3;
        float2 a0 = __half22float2(p0.a), b0 = __half22float2(p0.b);
        float2 a1 = __half22float2(p1.a), b1 = __half22float2(p1.b);
        float2 a2 = __half22float2(p2.a), b2 = __half22float2(p2.b);
        float2 a3 = __half22float2(p3.a), b3 = __half22float2(p3.b);
        acc.x += w0*a0.x; acc.y += w0*a0.y; acc.z += w0*b0.x; acc.w += w0*b0.y;
        acc.x += w1*a1.x; acc.y += w1*a1.y; acc.z += w1*b1.x; acc.w += w1*b1.y;
        acc.x += w2*a2.x; acc.y += w2*a2.y; acc.z += w2*b2.x; acc.w += w2*b2.y;
        acc.x += w3*a3.x; acc.y += w3*a3.y; acc.z += w3*b3.x; acc.w += w3*b3.y;
    }
    for (; i < end; i++){
        int s = g_srcs[i];
        float we = __expf(lrelu(g_as2[s*8 + w] + ad));
        h4 p = *(const h4*)(g_h2lin_h + (size_t)s*1024 + cofs);
        float2 a0 = __half22float2(p.a), b0 = __half22float2(p.b);
        dp += we;
        acc.x += we*a0.x; acc.y += we*a0.y; acc.z += we*b0.x; acc.w += we*b0.y;
    }
    if (l == 0) den_s[w] = dp + 1e-16f;
    __syncthreads();
    float inv = 1.f / den_s[w];
    float4 b4 = *(const float4*)(bias + cofs);
    h4 o;
    o.a = __floats2half2_rn(fmaxf(acc.x*inv + b4.x, 0.f), fmaxf(acc.y*inv + b4.y, 0.f));
    o.b = __floats2half2_rn(fmaxf(acc.z*inv + b4.z, 0.f), fmaxf(acc.w*inv + b4.w, 0.f));
    *(h4*)(g_h2h + (size_t)d*1024 + cofs) = o;
}

// ---------------- merged dueling heads GEMV (val 64 cols + adv 16 cols) ----
#define HK_SPAN 1024
#define HK_SUB  256
__global__ __launch_bounds__(256) void head_kernel(const float* __restrict__ Wval,
                                                   const float* __restrict__ Wadv){
    __shared__ __align__(16) float Hs[2][HK_SUB][8];   // 16KB, [buf][k][batch]
    int t = threadIdx.x;
    int w = t >> 5, l = t & 31;
    int kbase = blockIdx.x * HK_SPAN;
    int c4v = t & 15, jv = t >> 4;
    int c4a = t & 3,  ja = t >> 2;
    const float4* Wv4 = (const float4*)Wval;
    const float4* Wa4 = (const float4*)Wadv;

    ull vacc[4][4];                 // [batch-pair][col]
#pragma unroll
    for (int p = 0; p < 4; p++)
#pragma unroll
        for (int c = 0; c < 4; c++) vacc[p][c] = 0ull;
    float4 aa[8];
#pragma unroll
    for (int b = 0; b < 8; b++) aa[b] = make_float4(0.f,0.f,0.f,0.f);

    // preload tile 0 (transposed: Hs[k][b])
#pragma unroll
    for (int q = 0; q < 8; q++)
        Hs[0][t][q] = __half2float(g_h2h[(size_t)q*1048576 + kbase + t]);
    __syncthreads();

    for (int st = 0; st < HK_SPAN/HK_SUB; st++){
        int cur = st & 1;
        float rn[8];
        if (st < HK_SPAN/HK_SUB - 1){
#pragma unroll
            for (int q = 0; q < 8; q++)
                rn[q] = __half2float(g_h2h[(size_t)q*1048576 + kbase + (st+1)*HK_SUB + t]);
        }
        int k0g = kbase + st*HK_SUB;
        // ---- val: 64 cols, f32x2 over batch pairs ----
#pragma unroll 4
        for (int ii = 0; ii < HK_SUB/16; ii++){
            int k = jv + 16*ii;
            float4 w4 = __ldcs(&Wv4[(size_t)(k0g + k)*16 + c4v]);
            ull h01 = *(const ull*)&Hs[cur][k][0];
            ull h23 = *(const ull*)&Hs[cur][k][2];
            ull h45 = *(const ull*)&Hs[cur][k][4];
            ull h67 = *(const ull*)&Hs[cur][k][6];
            ull wx = pack2(w4.x, w4.x), wy = pack2(w4.y, w4.y);
            ull wz = pack2(w4.z, w4.z), ww = pack2(w4.w, w4.w);
            fma2(vacc[0][0], h01, wx); fma2(vacc[1][0], h23, wx);
            fma2(vacc[2][0], h45, wx); fma2(vacc[3][0], h67, wx);
            fma2(vacc[0][1], h01, wy); fma2(vacc[1][1], h23, wy);
            fma2(vacc[2][1], h45, wy); fma2(vacc[3][1], h67, wy);
            fma2(vacc[0][2], h01, wz); fma2(vacc[1][2], h23, wz);
            fma2(vacc[2][2], h45, wz); fma2(vacc[3][2], h67, wz);
            fma2(vacc[0][3], h01, ww); fma2(vacc[1][3], h23, ww);
            fma2(vacc[2][3], h45, ww); fma2(vacc[3][3], h67, ww);
        }
        // ---- adv: 16 cols ----
#pragma unroll
        for (int ii = 0; ii < HK_SUB/64; ii++){
            int k = ja + 64*ii;
            float4 w4 = __ldcs(&Wa4[(size_t)(k0g + k)*4 + c4a]);
#pragma unroll
            for (int b = 0; b < 8; b++){
                float h = Hs[cur][k][b];
                aa[b].x += h*w4.x; aa[b].y += h*w4.y;
                aa[b].z += h*w4.z; aa[b].w += h*w4.w;
            }
        }
        __syncthreads();
        if (st < HK_SPAN/HK_SUB - 1){
#pragma unroll
            for (int q = 0; q < 8; q++) Hs[1-cur][t][q] = rn[q];
            __syncthreads();
        }
    }

    // unpack val accumulators into per-batch float4
    float4 va[8];
#pragma unroll
    for (int p = 0; p < 4; p++){
        float lo, hi;
        unpack2(vacc[p][0], lo, hi); va[2*p].x = lo; va[2*p+1].x = hi;
        unpack2(vacc[p][1], lo, hi); va[2*p].y = lo; va[2*p+1].y = hi;
        unpack2(vacc[p][2], lo, hi); va[2*p].z = lo; va[2*p+1].z = hi;
        unpack2(vacc[p][3], lo, hi); va[2*p].w = lo; va[2*p+1].w = hi;
    }

    float4* red4 = (float4*)&Hs[0][0][0];   // reuse (all threads past final barrier)
    // ---- val reduce: jv pairs (lane offset 16), then across warps ----
#pragma unroll
    for (int b = 0; b < 8; b++) shfl_add(va[b], 16);
    if (l < 16){
#pragma unroll
        for (int b = 0; b < 8; b++) red4[(w*16 + l)*8 + b] = va[b];
    }
    __syncthreads();
    if (t < 128){
        int cc = t & 15, b = t >> 4;
        float4 s = make_float4(0.f,0.f,0.f,0.f);
#pragma unroll
        for (int ww = 0; ww < 8; ww++){
            float4 v = red4[(ww*16 + cc)*8 + b];
            s.x += v.x; s.y += v.y; s.z += v.z; s.w += v.w;
        }
        float* dst = g_valacc + b*64 + cc*4;
        atomicAdd(dst+0, s.x); atomicAdd(dst+1, s.y);
        atomicAdd(dst+2, s.z); atomicAdd(dst+3, s.w);
    }
    __syncthreads();
    // ---- adv reduce: within warp across ja (4,8,16), then warps ----
#pragma unroll
    for (int b = 0; b < 8; b++){
        shfl_add(aa[b], 4); shfl_add(aa[b], 8); shfl_add(aa[b], 16);
    }
    if (l < 4){
#pragma unroll
        for (int b = 0; b < 8; b++) red4[(w*4 + l)*8 + b] = aa[b];
    }
    __syncthreads();
    if (t < 32){
        int cc = t & 3, b = t >> 2;
        float4 s = make_float4(0.f,0.f,0.f,0.f);
#pragma unroll
        for (int ww = 0; ww < 8; ww++){
            float4 v = red4[(ww*4 + cc)*8 + b];
            s.x += v.x; s.y += v.y; s.z += v.z; s.w += v.w;
        }
        float* dst = g_advacc + b*16 + cc*4;
        atomicAdd(dst+0, s.x); atomicAdd(dst+1, s.y);
        atomicAdd(dst+2, s.z); atomicAdd(dst+3, s.w);
    }
}

// ---------------- finalize: val MLP + dueling combine ----------------
__global__ __launch_bounds__(512) void final_kernel(const float* __restrict__ adv_b,
                                                    const float* __restrict__ v1b,
                                                    const float* __restrict__ v2w,
                                                    const float* __restrict__ v2b,
                                                    const float* __restrict__ v3w,
                                                    const float* __restrict__ v3b,
                                                    float* __restrict__ out){
    int t = threadIdx.x;
    __shared__ float v1[512], v2s[512], vS[8], advs[128];
    v1[t] = fmaxf(g_valacc[t] + v1b[t & 63], 0.f);
    if (t < 128) advs[t] = fmaxf(g_advacc[t] + adv_b[t & 15], 0.f);
    __syncthreads();
    {
        int b = t >> 6, c = t & 63;
        float s2 = v2b[c];
        for (int k = 0; k < 64; k++) s2 += v1[b*64 + k] * v2w[k*64 + c];
        v2s[t] = fmaxf(s2, 0.f);
    }
    __syncthreads();
    if (t < 8){
        float s3 = v3b[0];
        for (int k = 0; k < 64; k++) s3 += v2s[t*64 + k] * v3w[k];
        vS[t] = s3;
    }
    __syncthreads();
    if (t < 128){
        int base = t & ~3;
        float mean = 0.25f*(advs[base] + advs[base+1] + advs[base+2] + advs[base+3]);
        out[t] = vS[t >> 4] + advs[t] - mean;
    }
}

// ---------------- launch ----------------
extern "C" void kernel_launch(void* const* d_in, const int* in_sizes, int n_in,
                              void* d_out, int out_size){
    const float* x      = (const float*)d_in[0];
    const void*  edge   = d_in[1];
    const float* W1     = (const float*)d_in[2];
    const float* a_src1 = (const float*)d_in[3];
    const float* a_dst1 = (const float*)d_in[4];
    const float* b1     = (const float*)d_in[5];
    const float* W2     = (const float*)d_in[6];
    const float* a_src2 = (const float*)d_in[7];
    const float* a_dst2 = (const float*)d_in[8];
    const float* b2     = (const float*)d_in[9];
    const float* adv_w  = (const float*)d_in[10];
    const float* adv_b  = (const float*)d_in[11];
    const float* val1_w = (const float*)d_in[12];
    const float* val1_b = (const float*)d_in[13];
    const float* val2_w = (const float*)d_in[14];
    const float* val2_b = (const float*)d_in[15];
    const float* val3_w = (const float*)d_in[16];
    const float* val3_b = (const float*)d_in[17];
    float* out = (float*)d_out;

    static cudaStream_t s1 = nullptr;
    static cudaEvent_t evF = nullptr, evJ = nullptr;
    if (s1 == nullptr){
        cudaStreamCreateWithFlags(&s1, cudaStreamNonBlocking);
        cudaEventCreateWithFlags(&evF, cudaEventDisableTiming);
        cudaEventCreateWithFlags(&evJ, cudaEventDisableTiming);
    }

    // fork: side stream runs prepM + lin1 while main stream builds CSR
    cudaEventRecord(evF, 0);
    cudaStreamWaitEvent(s1, evF, 0);

    prepM_kernel<<<64, 512, 0, s1>>>(W2, a_src2, a_dst2);
    lin1_kernel<<<NNODES/4, 256, 0, s1>>>(x, W1, a_src1, a_dst1);
    cudaEventRecord(evJ, s1);

    prep0_kernel<<<1, 512>>>((const int*)edge);
    count_kernel<<<NEDGES/256, 256>>>(edge);
    scan_kernel<<<1, 1024>>>();
    scatter_kernel<<<NEDGES/256, 256>>>(edge);

    cudaStreamWaitEvent(0, evJ, 0);   // join before agg1

    agg1_kernel<<<NNODES, 64>>>(b1);
    gemm2_kernel<<<dim3(16, 128), 256>>>(W2);
    agg2_kernel<<<NNODES, 256>>>(b2);

    head_kernel<<<1024, 256>>>(val1_w, adv_w);
    final_kernel<<<1, 512>>>(adv_b, val1_b, val2_w, val2_b, val3_w, val3_b, out);
}

// round 12
// speedup vs baseline: 1.0865x; 1.0578x over previous
#include <cuda_runtime.h>
#include <cuda_fp16.h>
#include <cstddef>

#define HEADS  8
#define NNODES 8192
#define NEDGES 131072
#define NEG    0.2f
#define CAP    128          // bucket capacity per dst (max degree ~40 for Binomial(131072,1/8192))

typedef unsigned long long ull;

// ---------------- scratch (static __device__, zero-initialized) -------------
__device__ float  g_h1lin[NNODES*64];
__device__ float  g_as1[NNODES*HEADS];
__device__ float  g_ad1[NNODES*HEADS];
__device__ float  g_h1[NNODES*64];
__device__ __half g_h2lin_h[(size_t)NNODES*1024];  // 16MB fp16 interchange
__device__ __half g_h2h[(size_t)NNODES*1024];      // 16MB fp16 interchange
__device__ float  g_as2[NNODES*HEADS];
__device__ float  g_ad2[NNODES*HEADS];
__device__ int    g_deg[NNODES];                    // zero at entry; re-zeroed by final
__device__ int    g_srcs[NNODES*CAP];               // 4MB bucket array
__device__ int    g_is64;
__device__ float  g_Ms[64*8];
__device__ float  g_Md[64*8];
__device__ float  g_valacc[512];                    // zero at entry; re-zeroed by final
__device__ float  g_advacc[128];

struct h4 { __half2 a, b; };

__device__ __forceinline__ float lrelu(float x){ return x > 0.f ? x : NEG*x; }

__device__ __forceinline__ void shfl_add(float4& v, int off){
    v.x += __shfl_down_sync(~0u, v.x, off);
    v.y += __shfl_down_sync(~0u, v.y, off);
    v.z += __shfl_down_sync(~0u, v.z, off);
    v.w += __shfl_down_sync(~0u, v.w, off);
}

// ---- packed fp32x2 helpers (Blackwell) ----
__device__ __forceinline__ ull pack2(float lo, float hi){
    ull r;
    asm("mov.b64 %0, {%1, %2};" : "=l"(r) : "r"(__float_as_uint(lo)), "r"(__float_as_uint(hi)));
    return r;
}
__device__ __forceinline__ void unpack2(ull v, float& lo, float& hi){
    unsigned int a, b;
    asm("mov.b64 {%0, %1}, %2;" : "=r"(a), "=r"(b) : "l"(v));
    lo = __uint_as_float(a); hi = __uint_as_float(b);
}
__device__ __forceinline__ void fma2(ull& d, ull a, ull b){
    asm("fma.rn.f32x2 %0, %1, %2, %0;" : "+l"(d) : "l"(a), "l"(b));
}

// ---------------- sniff: int64 vs int32 edge dtype ----------------
__global__ __launch_bounds__(512) void sniff_kernel(const int* __restrict__ e32){
    int t = threadIdx.x;
    __shared__ int nz;
    if (t == 0) nz = 0;
    __syncthreads();
    int v = 0;
    for (int i = t; i < 8192; i += 512) v |= e32[2*i+1];
    if (v) atomicOr(&nz, 1);
    __syncthreads();
    if (t == 0) g_is64 = (nz == 0) ? 1 : 0;
}

// ---------------- prepM: M = W2 @ a2 ----------------
__global__ __launch_bounds__(512) void prepM_kernel(const float* __restrict__ W2,
                                                    const float* __restrict__ a_s2,
                                                    const float* __restrict__ a_d2){
    int t = threadIdx.x;
    int k = blockIdx.x;   // 0..63
    __shared__ float sm[16][4];
    float w1  = W2[k*1024 + t];
    float w2v = W2[k*1024 + 512 + t];
    float p1s = w1  * a_s2[t];
    float p1d = w1  * a_d2[t];
    float p2s = w2v * a_s2[512 + t];
    float p2d = w2v * a_d2[512 + t];
#pragma unroll
    for (int off = 16; off; off >>= 1){
        p1s += __shfl_down_sync(~0u, p1s, off);
        p1d += __shfl_down_sync(~0u, p1d, off);
        p2s += __shfl_down_sync(~0u, p2s, off);
        p2d += __shfl_down_sync(~0u, p2d, off);
    }
    int w = t >> 5, l = t & 31;
    if (l == 0){ sm[w][0]=p1s; sm[w][1]=p1d; sm[w][2]=p2s; sm[w][3]=p2d; }
    __syncthreads();
    if (t < 8){
        float ms, md;
        if (t < 4){
            int b = t*4;
            ms = sm[b][0]+sm[b+1][0]+sm[b+2][0]+sm[b+3][0];
            md = sm[b][1]+sm[b+1][1]+sm[b+2][1]+sm[b+3][1];
        } else {
            int b = (t-4)*4;
            ms = sm[b][2]+sm[b+1][2]+sm[b+2][2]+sm[b+3][2];
            md = sm[b][3]+sm[b+1][3]+sm[b+2][3]+sm[b+3][3];
        }
        g_Ms[k*8 + t] = ms;
        g_Md[k*8 + t] = md;
    }
}

// ---------------- bucket scatter: one-pass CSR (count+place) ----------------
__global__ void scatter_kernel(const void* edge){
    int e = blockIdx.x*256 + threadIdx.x;
    if (e >= NEDGES) return;
    int s, d;
    if (g_is64){
        s = (int)((const long long*)edge)[e];
        d = (int)((const long long*)edge)[NEDGES + e];
    } else {
        s = ((const int*)edge)[e];
        d = ((const int*)edge)[NEDGES + e];
    }
    int pos = atomicAdd(&g_deg[d], 1);
    g_srcs[d*CAP + pos] = s;
}

// ---------------- layer 1 linear + attention logits (4 nodes / block) ------
__global__ __launch_bounds__(256) void lin1_kernel(const float* __restrict__ x,
                                                   const float* __restrict__ W1,
                                                   const float* __restrict__ a_s,
                                                   const float* __restrict__ a_d){
    __shared__ float Ws[16*64];
    __shared__ float xs[4][16];
    int t = threadIdx.x;
    int nl = t >> 6, tc = t & 63;
    int n = blockIdx.x*4 + nl;
    for (int i = t; i < 1024; i += 256) Ws[i] = W1[i];
    if (t < 64) xs[t >> 4][t & 15] = x[blockIdx.x*64 + t];
    __syncthreads();
    float acc = 0.f;
#pragma unroll
    for (int k = 0; k < 16; k++) acc += xs[nl][k] * Ws[k*64 + tc];
    g_h1lin[n*64 + tc] = acc;
    float ps = acc * a_s[tc];
    float pd = acc * a_d[tc];
#pragma unroll
    for (int off = 4; off; off >>= 1){
        ps += __shfl_down_sync(~0u, ps, off);
        pd += __shfl_down_sync(~0u, pd, off);
    }
    if ((tc & 7) == 0){
        g_as1[n*8 + (tc>>3)] = ps;
        g_ad1[n*8 + (tc>>3)] = pd;
    }
}

// ---------------- GAT1 aggregation (single-pass, no max) + alpha2 epilogue --
__global__ __launch_bounds__(64) void agg1_kernel(const float* __restrict__ bias){
    int d = blockIdx.x, t = threadIdx.x;
    int g = t >> 3, l8 = t & 7, l32 = t & 31, wid = t >> 5;
    __shared__ float adl[8], den_s[8];
    __shared__ float prS[2][8], prD[2][8];
    if (t < 8) adl[t] = g_ad1[d*8 + t];
    __syncthreads();
    int beg = d*CAP, end = beg + g_deg[d];
    float ad = adl[g];
    float ws0 = __expf(lrelu(g_as1[d*8 + g] + ad));     // self loop
    float acc = ws0 * g_h1lin[d*64 + t];
    float dp = ws0;
    int i = beg;
    for (; i + 4 <= end; i += 4){
        int s0 = g_srcs[i], s1 = g_srcs[i+1], s2 = g_srcs[i+2], s3 = g_srcs[i+3];
        float w0 = __expf(lrelu(g_as1[s0*8 + g] + ad));
        float w1 = __expf(lrelu(g_as1[s1*8 + g] + ad));
        float w2 = __expf(lrelu(g_as1[s2*8 + g] + ad));
        float w3 = __expf(lrelu(g_as1[s3*8 + g] + ad));
        float v0 = g_h1lin[s0*64 + t];
        float v1 = g_h1lin[s1*64 + t];
        float v2 = g_h1lin[s2*64 + t];
        float v3 = g_h1lin[s3*64 + t];
        dp += w0 + w1 + w2 + w3;
        acc += w0*v0; acc += w1*v1; acc += w2*v2; acc += w3*v3;
    }
    for (; i < end; i++){
        int s = g_srcs[i];
        float we = __expf(lrelu(g_as1[s*8 + g] + ad));
        dp += we;
        acc += we * g_h1lin[s*64 + t];
    }
    if (l8 == 0) den_s[g] = dp + 1e-16f;
    __syncthreads();
    float h1v = fmaxf(acc / den_s[g] + bias[t], 0.f);
    g_h1[d*64 + t] = h1v;
    // fused alpha2: as2[d,h] = h1[d,:] . Ms[:,h]
#pragma unroll
    for (int h = 0; h < 8; h++){
        float vs = h1v * g_Ms[t*8 + h];
        float vd = h1v * g_Md[t*8 + h];
#pragma unroll
        for (int off = 16; off; off >>= 1){
            vs += __shfl_down_sync(~0u, vs, off);
            vd += __shfl_down_sync(~0u, vd, off);
        }
        if (l32 == 0){ prS[wid][h] = vs; prD[wid][h] = vd; }
    }
    __syncthreads();
    if (t < 8){
        g_as2[d*8 + t] = prS[0][t] + prS[1][t];
        g_ad2[d*8 + t] = prD[0][t] + prD[1][t];
    }
}

// ---------------- layer 2 GEMM: h1[8192,64] @ W2[64,1024] -> fp16 ---------
__global__ __launch_bounds__(256) void gemm2_kernel(const float* __restrict__ W2){
    __shared__ float As[64][68];   // [k][m] (transposed)
    __shared__ float Bs[64][68];   // [k][n]
    int t = threadIdx.x;
    int n0 = blockIdx.x*64, m0 = blockIdx.y*64;
#pragma unroll
    for (int q = 0; q < 4; q++){
        int fid = q*256 + t;
        int row = fid >> 4, c4 = fid & 15;
        float4 a = *(const float4*)(g_h1 + (m0+row)*64 + c4*4);
        As[c4*4+0][row] = a.x; As[c4*4+1][row] = a.y;
        As[c4*4+2][row] = a.z; As[c4*4+3][row] = a.w;
        *(float4*)(&Bs[row][c4*4]) = *(const float4*)(W2 + row*1024 + n0 + c4*4);
    }
    __syncthreads();
    int tx = t & 15, ty = t >> 4;
    ull acc[4][2];
#pragma unroll
    for (int i = 0; i < 4; i++){ acc[i][0] = 0ull; acc[i][1] = 0ull; }
#pragma unroll
    for (int k = 0; k < 64; k++){
        float4 a4 = *(const float4*)&As[k][ty*4];
        ull b01 = *(const ull*)&Bs[k][tx*4];
        ull b23 = *(const ull*)&Bs[k][tx*4 + 2];
        ull a0 = pack2(a4.x, a4.x), a1 = pack2(a4.y, a4.y);
        ull a2 = pack2(a4.z, a4.z), a3 = pack2(a4.w, a4.w);
        fma2(acc[0][0], a0, b01); fma2(acc[0][1], a0, b23);
        fma2(acc[1][0], a1, b01); fma2(acc[1][1], a1, b23);
        fma2(acc[2][0], a2, b01); fma2(acc[2][1], a2, b23);
        fma2(acc[3][0], a3, b01); fma2(acc[3][1], a3, b23);
    }
#pragma unroll
    for (int i = 0; i < 4; i++){
        float4 o;
        unpack2(acc[i][0], o.x, o.y);
        unpack2(acc[i][1], o.z, o.w);
        h4 hh;
        hh.a = __floats2half2_rn(o.x, o.y);
        hh.b = __floats2half2_rn(o.z, o.w);
        *(h4*)(g_h2lin_h + (size_t)(m0 + ty*4 + i)*1024 + n0 + tx*4) = hh;
    }
}

// ---------------- GAT2 aggregation (single-pass, fp16 gather) --------------
__global__ __launch_bounds__(256) void agg2_kernel(const float* __restrict__ bias){
    int d = blockIdx.x, t = threadIdx.x;
    int w = t >> 5, l = t & 31;
    __shared__ float adl[8], den_s[8];
    if (t < 8) adl[t] = g_ad2[d*8 + t];
    __syncthreads();
    int beg = d*CAP, end = beg + g_deg[d];
    float ad = adl[w];
    float ws0 = __expf(lrelu(g_as2[d*8 + w] + ad));     // self loop
    int cofs = t*4;
    float4 acc;
    {
        h4 v = *(const h4*)(g_h2lin_h + (size_t)d*1024 + cofs);
        float2 f0 = __half22float2(v.a), f1 = __half22float2(v.b);
        acc.x = ws0*f0.x; acc.y = ws0*f0.y; acc.z = ws0*f1.x; acc.w = ws0*f1.y;
    }
    float dp = ws0;
    int i = beg;
    for (; i + 4 <= end; i += 4){
        int s0 = g_srcs[i], s1 = g_srcs[i+1], s2 = g_srcs[i+2], s3 = g_srcs[i+3];
        float w0 = __expf(lrelu(g_as2[s0*8 + w] + ad));
        float w1 = __expf(lrelu(g_as2[s1*8 + w] + ad));
        float w2 = __expf(lrelu(g_as2[s2*8 + w] + ad));
        float w3 = __expf(lrelu(g_as2[s3*8 + w] + ad));
        h4 p0 = *(const h4*)(g_h2lin_h + (size_t)s0*1024 + cofs);
        h4 p1 = *(const h4*)(g_h2lin_h + (size_t)s1*1024 + cofs);
        h4 p2 = *(const h4*)(g_h2lin_h + (size_t)s2*1024 + cofs);
        h4 p3 = *(const h4*)(g_h2lin_h + (size_t)s3*1024 + cofs);
        dp += w0 + w1 + w2 + w3;
        float2 a0 = __half22float2(p0.a), b0 = __half22float2(p0.b);
        float2 a1 = __half22float2(p1.a), b1 = __half22float2(p1.b);
        float2 a2 = __half22float2(p2.a), b2 = __half22float2(p2.b);
        float2 a3 = __half22float2(p3.a), b3 = __half22float2(p3.b);
        acc.x += w0*a0.x; acc.y += w0*a0.y; acc.z += w0*b0.x; acc.w += w0*b0.y;
        acc.x += w1*a1.x; acc.y += w1*a1.y; acc.z += w1*b1.x; acc.w += w1*b1.y;
        acc.x += w2*a2.x; acc.y += w2*a2.y; acc.z += w2*b2.x; acc.w += w2*b2.y;
        acc.x += w3*a3.x; acc.y += w3*a3.y; acc.z += w3*b3.x; acc.w += w3*b3.y;
    }
    for (; i < end; i++){
        int s = g_srcs[i];
        float we = __expf(lrelu(g_as2[s*8 + w] + ad));
        h4 p = *(const h4*)(g_h2lin_h + (size_t)s*1024 + cofs);
        float2 a0 = __half22float2(p.a), b0 = __half22float2(p.b);
        dp += we;
        acc.x += we*a0.x; acc.y += we*a0.y; acc.z += we*b0.x; acc.w += we*b0.y;
    }
    if (l == 0) den_s[w] = dp + 1e-16f;
    __syncthreads();
    float inv = 1.f / den_s[w];
    float4 b4 = *(const float4*)(bias + cofs);
    h4 o;
    o.a = __floats2half2_rn(fmaxf(acc.x*inv + b4.x, 0.f), fmaxf(acc.y*inv + b4.y, 0.f));
    o.b = __floats2half2_rn(fmaxf(acc.z*inv + b4.z, 0.f), fmaxf(acc.w*inv + b4.w, 0.f));
    *(h4*)(g_h2h + (size_t)d*1024 + cofs) = o;
}

// ---------------- merged dueling heads GEMV (val 64 cols + adv 16 cols) ----
#define HK_SPAN 1024
#define HK_SUB  256
__global__ __launch_bounds__(256) void head_kernel(const float* __restrict__ Wval,
                                                   const float* __restrict__ Wadv){
    __shared__ __align__(16) float Hs[2][HK_SUB][8];   // 16KB, [buf][k][batch]
    int t = threadIdx.x;
    int w = t >> 5, l = t & 31;
    int kbase = blockIdx.x * HK_SPAN;
    int c4v = t & 15, jv = t >> 4;
    int c4a = t & 3,  ja = t >> 2;
    const float4* Wv4 = (const float4*)Wval;
    const float4* Wa4 = (const float4*)Wadv;

    ull vacc[4][4];                 // [batch-pair][col]
#pragma unroll
    for (int p = 0; p < 4; p++)
#pragma unroll
        for (int c = 0; c < 4; c++) vacc[p][c] = 0ull;
    float4 aa[8];
#pragma unroll
    for (int b = 0; b < 8; b++) aa[b] = make_float4(0.f,0.f,0.f,0.f);

    // preload tile 0 (transposed: Hs[k][b])
#pragma unroll
    for (int q = 0; q < 8; q++)
        Hs[0][t][q] = __half2float(g_h2h[(size_t)q*1048576 + kbase + t]);
    __syncthreads();

    for (int st = 0; st < HK_SPAN/HK_SUB; st++){
        int cur = st & 1;
        float rn[8];
        if (st < HK_SPAN/HK_SUB - 1){
#pragma unroll
            for (int q = 0; q < 8; q++)
                rn[q] = __half2float(g_h2h[(size_t)q*1048576 + kbase + (st+1)*HK_SUB + t]);
        }
        int k0g = kbase + st*HK_SUB;
        // ---- val: 64 cols, f32x2 over batch pairs ----
#pragma unroll 4
        for (int ii = 0; ii < HK_SUB/16; ii++){
            int k = jv + 16*ii;
            float4 w4 = __ldcs(&Wv4[(size_t)(k0g + k)*16 + c4v]);
            ull h01 = *(const ull*)&Hs[cur][k][0];
            ull h23 = *(const ull*)&Hs[cur][k][2];
            ull h45 = *(const ull*)&Hs[cur][k][4];
            ull h67 = *(const ull*)&Hs[cur][k][6];
            ull wx = pack2(w4.x, w4.x), wy = pack2(w4.y, w4.y);
            ull wz = pack2(w4.z, w4.z), ww = pack2(w4.w, w4.w);
            fma2(vacc[0][0], h01, wx); fma2(vacc[1][0], h23, wx);
            fma2(vacc[2][0], h45, wx); fma2(vacc[3][0], h67, wx);
            fma2(vacc[0][1], h01, wy); fma2(vacc[1][1], h23, wy);
            fma2(vacc[2][1], h45, wy); fma2(vacc[3][1], h67, wy);
            fma2(vacc[0][2], h01, wz); fma2(vacc[1][2], h23, wz);
            fma2(vacc[2][2], h45, wz); fma2(vacc[3][2], h67, wz);
            fma2(vacc[0][3], h01, ww); fma2(vacc[1][3], h23, ww);
            fma2(vacc[2][3], h45, ww); fma2(vacc[3][3], h67, ww);
        }
        // ---- adv: 16 cols ----
#pragma unroll
        for (int ii = 0; ii < HK_SUB/64; ii++){
            int k = ja + 64*ii;
            float4 w4 = __ldcs(&Wa4[(size_t)(k0g + k)*4 + c4a]);
#pragma unroll
            for (int b = 0; b < 8; b++){
                float h = Hs[cur][k][b];
                aa[b].x += h*w4.x; aa[b].y += h*w4.y;
                aa[b].z += h*w4.z; aa[b].w += h*w4.w;
            }
        }
        __syncthreads();
        if (st < HK_SPAN/HK_SUB - 1){
#pragma unroll
            for (int q = 0; q < 8; q++) Hs[1-cur][t][q] = rn[q];
            __syncthreads();
        }
    }

    // unpack val accumulators into per-batch float4
    float4 va[8];
#pragma unroll
    for (int p = 0; p < 4; p++){
        float lo, hi;
        unpack2(vacc[p][0], lo, hi); va[2*p].x = lo; va[2*p+1].x = hi;
        unpack2(vacc[p][1], lo, hi); va[2*p].y = lo; va[2*p+1].y = hi;
        unpack2(vacc[p][2], lo, hi); va[2*p].z = lo; va[2*p+1].z = hi;
        unpack2(vacc[p][3], lo, hi); va[2*p].w = lo; va[2*p+1].w = hi;
    }

    float4* red4 = (float4*)&Hs[0][0][0];   // reuse (all threads past final barrier)
    // ---- val reduce: jv pairs (lane offset 16), then across warps ----
#pragma unroll
    for (int b = 0; b < 8; b++) shfl_add(va[b], 16);
    if (l < 16){
#pragma unroll
        for (int b = 0; b < 8; b++) red4[(w*16 + l)*8 + b] = va[b];
    }
    __syncthreads();
    if (t < 128){
        int cc = t & 15, b = t >> 4;
        float4 s = make_float4(0.f,0.f,0.f,0.f);
#pragma unroll
        for (int ww = 0; ww < 8; ww++){
            float4 v = red4[(ww*16 + cc)*8 + b];
            s.x += v.x; s.y += v.y; s.z += v.z; s.w += v.w;
        }
        float* dst = g_valacc + b*64 + cc*4;
        atomicAdd(dst+0, s.x); atomicAdd(dst+1, s.y);
        atomicAdd(dst+2, s.z); atomicAdd(dst+3, s.w);
    }
    __syncthreads();
    // ---- adv reduce: within warp across ja (4,8,16), then warps ----
#pragma unroll
    for (int b = 0; b < 8; b++){
        shfl_add(aa[b], 4); shfl_add(aa[b], 8); shfl_add(aa[b], 16);
    }
    if (l < 4){
#pragma unroll
        for (int b = 0; b < 8; b++) red4[(w*4 + l)*8 + b] = aa[b];
    }
    __syncthreads();
    if (t < 32){
        int cc = t & 3, b = t >> 2;
        float4 s = make_float4(0.f,0.f,0.f,0.f);
#pragma unroll
        for (int ww = 0; ww < 8; ww++){
            float4 v = red4[(ww*4 + cc)*8 + b];
            s.x += v.x; s.y += v.y; s.z += v.z; s.w += v.w;
        }
        float* dst = g_advacc + b*16 + cc*4;
        atomicAdd(dst+0, s.x); atomicAdd(dst+1, s.y);
        atomicAdd(dst+2, s.z); atomicAdd(dst+3, s.w);
    }
}

// ---------- finalize: val MLP + dueling combine + re-zero accumulators -----
__global__ __launch_bounds__(512) void final_kernel(const float* __restrict__ adv_b,
                                                    const float* __restrict__ v1b,
                                                    const float* __restrict__ v2w,
                                                    const float* __restrict__ v2b,
                                                    const float* __restrict__ v3w,
                                                    const float* __restrict__ v3b,
                                                    float* __restrict__ out){
    int t = threadIdx.x;
    __shared__ float v1[512], v2s[512], vS[8], advs[128];
    v1[t] = fmaxf(g_valacc[t] + v1b[t & 63], 0.f);
    g_valacc[t] = 0.f;                                  // re-zero for next call
    if (t < 128){
        advs[t] = fmaxf(g_advacc[t] + adv_b[t & 15], 0.f);
        g_advacc[t] = 0.f;
    }
#pragma unroll
    for (int i = t; i < NNODES; i += 512) g_deg[i] = 0; // re-zero for next call
    __syncthreads();
    {
        int b = t >> 6, c = t & 63;
        float s2 = v2b[c];
        for (int k = 0; k < 64; k++) s2 += v1[b*64 + k] * v2w[k*64 + c];
        v2s[t] = fmaxf(s2, 0.f);
    }
    __syncthreads();
    if (t < 8){
        float s3 = v3b[0];
        for (int k = 0; k < 64; k++) s3 += v2s[t*64 + k] * v3w[k];
        vS[t] = s3;
    }
    __syncthreads();
    if (t < 128){
        int base = t & ~3;
        float mean = 0.25f*(advs[base] + advs[base+1] + advs[base+2] + advs[base+3]);
        out[t] = vS[t >> 4] + advs[t] - mean;
    }
}

// ---------------- launch ----------------
extern "C" void kernel_launch(void* const* d_in, const int* in_sizes, int n_in,
                              void* d_out, int out_size){
    const float* x      = (const float*)d_in[0];
    const void*  edge   = d_in[1];
    const float* W1     = (const float*)d_in[2];
    const float* a_src1 = (const float*)d_in[3];
    const float* a_dst1 = (const float*)d_in[4];
    const float* b1     = (const float*)d_in[5];
    const float* W2     = (const float*)d_in[6];
    const float* a_src2 = (const float*)d_in[7];
    const float* a_dst2 = (const float*)d_in[8];
    const float* b2     = (const float*)d_in[9];
    const float* adv_w  = (const float*)d_in[10];
    const float* adv_b  = (const float*)d_in[11];
    const float* val1_w = (const float*)d_in[12];
    const float* val1_b = (const float*)d_in[13];
    const float* val2_w = (const float*)d_in[14];
    const float* val2_b = (const float*)d_in[15];
    const float* val3_w = (const float*)d_in[16];
    const float* val3_b = (const float*)d_in[17];
    float* out = (float*)d_out;

    sniff_kernel<<<1, 512>>>((const int*)edge);
    scatter_kernel<<<NEDGES/256, 256>>>(edge);          // one-pass bucket CSR
    prepM_kernel<<<64, 512>>>(W2, a_src2, a_dst2);
    lin1_kernel<<<NNODES/4, 256>>>(x, W1, a_src1, a_dst1);

    agg1_kernel<<<NNODES, 64>>>(b1);
    gemm2_kernel<<<dim3(16, 128), 256>>>(W2);
    agg2_kernel<<<NNODES, 256>>>(b2);

    head_kernel<<<1024, 256>>>(val1_w, adv_w);
    final_kernel<<<1, 512>>>(adv_b, val1_b, val2_w, val2_b, val3_w, val3_b, out);
}

// round 13
// speedup vs baseline: 1.0965x; 1.0093x over previous
#include <cuda_runtime.h>
#include <cuda_fp16.h>
#include <cstddef>

#define HEADS  8
#define NNODES 8192
#define NEDGES 131072
#define NEG    0.2f
#define CAP    128          // bucket capacity per dst (max degree ~40 for Binomial(131072,1/8192))

typedef unsigned long long ull;

// ---------------- scratch (static __device__, zero-initialized) -------------
__device__ float  g_h1lin[NNODES*64];
__device__ float  g_as1[NNODES*HEADS];
__device__ float  g_ad1[NNODES*HEADS];
__device__ float  g_h1[NNODES*64];
__device__ __half g_h2lin_h[(size_t)NNODES*1024];  // 16MB fp16 interchange
__device__ __half g_h2h[(size_t)NNODES*1024];      // 16MB fp16 interchange
__device__ float  g_as2[NNODES*HEADS];
__device__ float  g_ad2[NNODES*HEADS];
__device__ int    g_deg[NNODES];                    // zero at entry; re-zeroed by final
__device__ int    g_srcs[NNODES*CAP];               // 4MB bucket array
__device__ int    g_is64;
__device__ float  g_Ms[64*8];
__device__ float  g_Md[64*8];
__device__ float  g_M1s[16*8];
__device__ float  g_M1d[16*8];
__device__ float  g_valacc[512];                    // zero at entry; re-zeroed by final
__device__ float  g_advacc[128];

struct h4 { __half2 a, b; };

__device__ __forceinline__ float lrelu(float x){ return x > 0.f ? x : NEG*x; }

__device__ __forceinline__ void shfl_add(float4& v, int off){
    v.x += __shfl_down_sync(~0u, v.x, off);
    v.y += __shfl_down_sync(~0u, v.y, off);
    v.z += __shfl_down_sync(~0u, v.z, off);
    v.w += __shfl_down_sync(~0u, v.w, off);
}

// ---- packed fp32x2 helpers (Blackwell) ----
__device__ __forceinline__ ull pack2(float lo, float hi){
    ull r;
    asm("mov.b64 %0, {%1, %2};" : "=l"(r) : "r"(__float_as_uint(lo)), "r"(__float_as_uint(hi)));
    return r;
}
__device__ __forceinline__ void unpack2(ull v, float& lo, float& hi){
    unsigned int a, b;
    asm("mov.b64 {%0, %1}, %2;" : "=r"(a), "=r"(b) : "l"(v));
    lo = __uint_as_float(a); hi = __uint_as_float(b);
}
__device__ __forceinline__ void fma2(ull& d, ull a, ull b){
    asm("fma.rn.f32x2 %0, %1, %2, %0;" : "+l"(d) : "l"(a), "l"(b));
}

// ------ prep: blocks 0..63 = M(W2@a2); block 64 = sniff; block 65 = M1 ------
__global__ __launch_bounds__(512) void prep_kernel(const int* __restrict__ e32,
                                                   const float* __restrict__ W1,
                                                   const float* __restrict__ a_s1,
                                                   const float* __restrict__ a_d1,
                                                   const float* __restrict__ W2,
                                                   const float* __restrict__ a_s2,
                                                   const float* __restrict__ a_d2){
    int t = threadIdx.x;
    int bk = blockIdx.x;
    if (bk == 64){
        __shared__ int nz;
        if (t == 0) nz = 0;
        __syncthreads();
        int v = 0;
        for (int i = t; i < 8192; i += 512) v |= e32[2*i+1];
        if (v) atomicOr(&nz, 1);
        __syncthreads();
        if (t == 0) g_is64 = (nz == 0) ? 1 : 0;
        return;
    }
    if (bk == 65){
        // M1s[k][h] = sum_c W1[k][h*8+c] * a_s1[h*8+c]
        if (t < 128){
            int k = t >> 3, h = t & 7;
            float ms = 0.f, md = 0.f;
#pragma unroll
            for (int c = 0; c < 8; c++){
                float wv = W1[k*64 + h*8 + c];
                ms += wv * a_s1[h*8 + c];
                md += wv * a_d1[h*8 + c];
            }
            g_M1s[k*8 + h] = ms;
            g_M1d[k*8 + h] = md;
        }
        return;
    }
    int k = bk;   // 0..63
    __shared__ float sm[16][4];
    float w1  = W2[k*1024 + t];
    float w2v = W2[k*1024 + 512 + t];
    float p1s = w1  * a_s2[t];
    float p1d = w1  * a_d2[t];
    float p2s = w2v * a_s2[512 + t];
    float p2d = w2v * a_d2[512 + t];
#pragma unroll
    for (int off = 16; off; off >>= 1){
        p1s += __shfl_down_sync(~0u, p1s, off);
        p1d += __shfl_down_sync(~0u, p1d, off);
        p2s += __shfl_down_sync(~0u, p2s, off);
        p2d += __shfl_down_sync(~0u, p2d, off);
    }
    int w = t >> 5, l = t & 31;
    if (l == 0){ sm[w][0]=p1s; sm[w][1]=p1d; sm[w][2]=p2s; sm[w][3]=p2d; }
    __syncthreads();
    if (t < 8){
        float ms, md;
        if (t < 4){
            int b = t*4;
            ms = sm[b][0]+sm[b+1][0]+sm[b+2][0]+sm[b+3][0];
            md = sm[b][1]+sm[b+1][1]+sm[b+2][1]+sm[b+3][1];
        } else {
            int b = (t-4)*4;
            ms = sm[b][2]+sm[b+1][2]+sm[b+2][2]+sm[b+3][2];
            md = sm[b][3]+sm[b+1][3]+sm[b+2][3]+sm[b+3][3];
        }
        g_Ms[k*8 + t] = ms;
        g_Md[k*8 + t] = md;
    }
}

// ---------------- bucket scatter: one-pass CSR (count+place) ----------------
__global__ void scatter_kernel(const void* edge){
    int e = blockIdx.x*256 + threadIdx.x;
    if (e >= NEDGES) return;
    int s, d;
    if (g_is64){
        s = (int)((const long long*)edge)[e];
        d = (int)((const long long*)edge)[NEDGES + e];
    } else {
        s = ((const int*)edge)[e];
        d = ((const int*)edge)[NEDGES + e];
    }
    int pos = atomicAdd(&g_deg[d], 1);
    g_srcs[d*CAP + pos] = s;
}

// ------- layer 1 linear + logits via M1 (no shuffles; 4 nodes/block) -------
__global__ __launch_bounds__(256) void lin1_kernel(const float* __restrict__ x,
                                                   const float* __restrict__ W1){
    __shared__ float Ws[16*64];
    __shared__ float xs[4][16];
    int t = threadIdx.x;
    int nl = t >> 6, tc = t & 63;
    int n = blockIdx.x*4 + nl;
    for (int i = t; i < 1024; i += 256) Ws[i] = W1[i];
    if (t < 64) xs[t >> 4][t & 15] = x[blockIdx.x*64 + t];
    __syncthreads();
    float acc = 0.f;
#pragma unroll
    for (int k = 0; k < 16; k++) acc += xs[nl][k] * Ws[k*64 + tc];
    g_h1lin[n*64 + tc] = acc;
    // logits: as1[n,h] = x[n,:] . M1s[:,h]  (threads 0..7: as, 8..15: ad)
    if (tc < 16){
        int h = tc & 7;
        const float* M = (tc < 8) ? g_M1s : g_M1d;
        float s = 0.f;
#pragma unroll
        for (int k = 0; k < 16; k++) s += xs[nl][k] * M[k*8 + h];
        if (tc < 8) g_as1[n*8 + h] = s;
        else        g_ad1[n*8 + h] = s;
    }
}

// ---------------- GAT1 aggregation (single-pass, no max) + alpha2 epilogue --
__global__ __launch_bounds__(64) void agg1_kernel(const float* __restrict__ bias){
    int d = blockIdx.x, t = threadIdx.x;
    int g = t >> 3, l8 = t & 7, l32 = t & 31, wid = t >> 5;
    __shared__ float adl[8], den_s[8];
    __shared__ float prS[2][8], prD[2][8];
    if (t < 8) adl[t] = g_ad1[d*8 + t];
    __syncthreads();
    int beg = d*CAP, end = beg + g_deg[d];
    float ad = adl[g];
    float ws0 = __expf(lrelu(g_as1[d*8 + g] + ad));     // self loop
    float acc = ws0 * g_h1lin[d*64 + t];
    float dp = ws0;
    int i = beg;
    for (; i + 4 <= end; i += 4){
        int s0 = g_srcs[i], s1 = g_srcs[i+1], s2 = g_srcs[i+2], s3 = g_srcs[i+3];
        float w0 = __expf(lrelu(g_as1[s0*8 + g] + ad));
        float w1 = __expf(lrelu(g_as1[s1*8 + g] + ad));
        float w2 = __expf(lrelu(g_as1[s2*8 + g] + ad));
        float w3 = __expf(lrelu(g_as1[s3*8 + g] + ad));
        float v0 = g_h1lin[s0*64 + t];
        float v1 = g_h1lin[s1*64 + t];
        float v2 = g_h1lin[s2*64 + t];
        float v3 = g_h1lin[s3*64 + t];
        dp += w0 + w1 + w2 + w3;
        acc += w0*v0; acc += w1*v1; acc += w2*v2; acc += w3*v3;
    }
    for (; i < end; i++){
        int s = g_srcs[i];
        float we = __expf(lrelu(g_as1[s*8 + g] + ad));
        dp += we;
        acc += we * g_h1lin[s*64 + t];
    }
    if (l8 == 0) den_s[g] = dp + 1e-16f;
    __syncthreads();
    float h1v = fmaxf(acc / den_s[g] + bias[t], 0.f);
    g_h1[d*64 + t] = h1v;
    // fused alpha2: as2[d,h] = h1[d,:] . Ms[:,h]
#pragma unroll
    for (int h = 0; h < 8; h++){
        float vs = h1v * g_Ms[t*8 + h];
        float vd = h1v * g_Md[t*8 + h];
#pragma unroll
        for (int off = 16; off; off >>= 1){
            vs += __shfl_down_sync(~0u, vs, off);
            vd += __shfl_down_sync(~0u, vd, off);
        }
        if (l32 == 0){ prS[wid][h] = vs; prD[wid][h] = vd; }
    }
    __syncthreads();
    if (t < 8){
        g_as2[d*8 + t] = prS[0][t] + prS[1][t];
        g_ad2[d*8 + t] = prD[0][t] + prD[1][t];
    }
}

// ---------------- layer 2 GEMM: h1[8192,64] @ W2[64,1024] -> fp16 ---------
__global__ __launch_bounds__(256) void gemm2_kernel(const float* __restrict__ W2){
    __shared__ float As[64][68];   // [k][m] (transposed)
    __shared__ float Bs[64][68];   // [k][n]
    int t = threadIdx.x;
    int n0 = blockIdx.x*64, m0 = blockIdx.y*64;
#pragma unroll
    for (int q = 0; q < 4; q++){
        int fid = q*256 + t;
        int row = fid >> 4, c4 = fid & 15;
        float4 a = *(const float4*)(g_h1 + (m0+row)*64 + c4*4);
        As[c4*4+0][row] = a.x; As[c4*4+1][row] = a.y;
        As[c4*4+2][row] = a.z; As[c4*4+3][row] = a.w;
        *(float4*)(&Bs[row][c4*4]) = *(const float4*)(W2 + row*1024 + n0 + c4*4);
    }
    __syncthreads();
    int tx = t & 15, ty = t >> 4;
    ull acc[4][2];
#pragma unroll
    for (int i = 0; i < 4; i++){ acc[i][0] = 0ull; acc[i][1] = 0ull; }
#pragma unroll
    for (int k = 0; k < 64; k++){
        float4 a4 = *(const float4*)&As[k][ty*4];
        ull b01 = *(const ull*)&Bs[k][tx*4];
        ull b23 = *(const ull*)&Bs[k][tx*4 + 2];
        ull a0 = pack2(a4.x, a4.x), a1 = pack2(a4.y, a4.y);
        ull a2 = pack2(a4.z, a4.z), a3 = pack2(a4.w, a4.w);
        fma2(acc[0][0], a0, b01); fma2(acc[0][1], a0, b23);
        fma2(acc[1][0], a1, b01); fma2(acc[1][1], a1, b23);
        fma2(acc[2][0], a2, b01); fma2(acc[2][1], a2, b23);
        fma2(acc[3][0], a3, b01); fma2(acc[3][1], a3, b23);
    }
#pragma unroll
    for (int i = 0; i < 4; i++){
        float4 o;
        unpack2(acc[i][0], o.x, o.y);
        unpack2(acc[i][1], o.z, o.w);
        h4 hh;
        hh.a = __floats2half2_rn(o.x, o.y);
        hh.b = __floats2half2_rn(o.z, o.w);
        *(h4*)(g_h2lin_h + (size_t)(m0 + ty*4 + i)*1024 + n0 + tx*4) = hh;
    }
}

// ---------------- GAT2 aggregation (single-pass, fp16 gather) --------------
__global__ __launch_bounds__(256) void agg2_kernel(const float* __restrict__ bias){
    int d = blockIdx.x, t = threadIdx.x;
    int w = t >> 5, l = t & 31;
    __shared__ float adl[8], den_s[8];
    if (t < 8) adl[t] = g_ad2[d*8 + t];
    __syncthreads();
    int beg = d*CAP, end = beg + g_deg[d];
    float ad = adl[w];
    float ws0 = __expf(lrelu(g_as2[d*8 + w] + ad));     // self loop
    int cofs = t*4;
    float4 acc;
    {
        h4 v = *(const h4*)(g_h2lin_h + (size_t)d*1024 + cofs);
        float2 f0 = __half22float2(v.a), f1 = __half22float2(v.b);
        acc.x = ws0*f0.x; acc.y = ws0*f0.y; acc.z = ws0*f1.x; acc.w = ws0*f1.y;
    }
    float dp = ws0;
    int i = beg;
    for (; i + 4 <= end; i += 4){
        int s0 = g_srcs[i], s1 = g_srcs[i+1], s2 = g_srcs[i+2], s3 = g_srcs[i+3];
        float w0 = __expf(lrelu(g_as2[s0*8 + w] + ad));
        float w1 = __expf(lrelu(g_as2[s1*8 + w] + ad));
        float w2 = __expf(lrelu(g_as2[s2*8 + w] + ad));
        float w3 = __expf(lrelu(g_as2[s3*8 + w] + ad));
        h4 p0 = *(const h4*)(g_h2lin_h + (size_t)s0*1024 + cofs);
        h4 p1 = *(const h4*)(g_h2lin_h + (size_t)s1*1024 + cofs);
        h4 p2 = *(const h4*)(g_h2lin_h + (size_t)s2*1024 + cofs);
        h4 p3 = *(const h4*)(g_h2lin_h + (size_t)s3*1024 + cofs);
        dp += w0 + w1 + w2 + w3;
        float2 a0 = __half22float2(p0.a), b0 = __half22float2(p0.b);
        float2 a1 = __half22float2(p1.a), b1 = __half22float2(p1.b);
        float2 a2 = __half22float2(p2.a), b2 = __half22float2(p2.b);
        float2 a3 = __half22float2(p3.a), b3 = __half22float2(p3.b);
        acc.x += w0*a0.x; acc.y += w0*a0.y; acc.z += w0*b0.x; acc.w += w0*b0.y;
        acc.x += w1*a1.x; acc.y += w1*a1.y; acc.z += w1*b1.x; acc.w += w1*b1.y;
        acc.x += w2*a2.x; acc.y += w2*a2.y; acc.z += w2*b2.x; acc.w += w2*b2.y;
        acc.x += w3*a3.x; acc.y += w3*a3.y; acc.z += w3*b3.x; acc.w += w3*b3.y;
    }
    for (; i < end; i++){
        int s = g_srcs[i];
        float we = __expf(lrelu(g_as2[s*8 + w] + ad));
        h4 p = *(const h4*)(g_h2lin_h + (size_t)s*1024 + cofs);
        float2 a0 = __half22float2(p.a), b0 = __half22float2(p.b);
        dp += we;
        acc.x += we*a0.x; acc.y += we*a0.y; acc.z += we*b0.x; acc.w += we*b0.y;
    }
    if (l == 0) den_s[w] = dp + 1e-16f;
    __syncthreads();
    float inv = 1.f / den_s[w];
    float4 b4 = *(const float4*)(bias + cofs);
    h4 o;
    o.a = __floats2half2_rn(fmaxf(acc.x*inv + b4.x, 0.f), fmaxf(acc.y*inv + b4.y, 0.f));
    o.b = __floats2half2_rn(fmaxf(acc.z*inv + b4.z, 0.f), fmaxf(acc.w*inv + b4.w, 0.f));
    *(h4*)(g_h2h + (size_t)d*1024 + cofs) = o;
}

// ---------------- merged dueling heads GEMV (val 64 cols + adv 16 cols) ----
#define HK_SPAN 1024
#define HK_SUB  256
__global__ __launch_bounds__(256) void head_kernel(const float* __restrict__ Wval,
                                                   const float* __restrict__ Wadv){
    __shared__ __align__(16) float Hs[2][HK_SUB][8];   // 16KB, [buf][k][batch]
    int t = threadIdx.x;
    int w = t >> 5, l = t & 31;
    int kbase = blockIdx.x * HK_SPAN;
    int c4v = t & 15, jv = t >> 4;
    int c4a = t & 3,  ja = t >> 2;
    const float4* Wv4 = (const float4*)Wval;
    const float4* Wa4 = (const float4*)Wadv;

    ull vacc[4][4];                 // [batch-pair][col]
#pragma unroll
    for (int p = 0; p < 4; p++)
#pragma unroll
        for (int c = 0; c < 4; c++) vacc[p][c] = 0ull;
    float4 aa[8];
#pragma unroll
    for (int b = 0; b < 8; b++) aa[b] = make_float4(0.f,0.f,0.f,0.f);

    // preload tile 0 (transposed: Hs[k][b])
#pragma unroll
    for (int q = 0; q < 8; q++)
        Hs[0][t][q] = __half2float(g_h2h[(size_t)q*1048576 + kbase + t]);
    __syncthreads();

    for (int st = 0; st < HK_SPAN/HK_SUB; st++){
        int cur = st & 1;
        float rn[8];
        if (st < HK_SPAN/HK_SUB - 1){
#pragma unroll
            for (int q = 0; q < 8; q++)
                rn[q] = __half2float(g_h2h[(size_t)q*1048576 + kbase + (st+1)*HK_SUB + t]);
        }
        int k0g = kbase + st*HK_SUB;
        // ---- val: 64 cols, f32x2 over batch pairs ----
#pragma unroll 4
        for (int ii = 0; ii < HK_SUB/16; ii++){
            int k = jv + 16*ii;
            float4 w4 = __ldcs(&Wv4[(size_t)(k0g + k)*16 + c4v]);
            ull h01 = *(const ull*)&Hs[cur][k][0];
            ull h23 = *(const ull*)&Hs[cur][k][2];
            ull h45 = *(const ull*)&Hs[cur][k][4];
            ull h67 = *(const ull*)&Hs[cur][k][6];
            ull wx = pack2(w4.x, w4.x), wy = pack2(w4.y, w4.y);
            ull wz = pack2(w4.z, w4.z), ww = pack2(w4.w, w4.w);
            fma2(vacc[0][0], h01, wx); fma2(vacc[1][0], h23, wx);
            fma2(vacc[2][0], h45, wx); fma2(vacc[3][0], h67, wx);
            fma2(vacc[0][1], h01, wy); fma2(vacc[1][1], h23, wy);
            fma2(vacc[2][1], h45, wy); fma2(vacc[3][1], h67, wy);
            fma2(vacc[0][2], h01, wz); fma2(vacc[1][2], h23, wz);
            fma2(vacc[2][2], h45, wz); fma2(vacc[3][2], h67, wz);
            fma2(vacc[0][3], h01, ww); fma2(vacc[1][3], h23, ww);
            fma2(vacc[2][3], h45, ww); fma2(vacc[3][3], h67, ww);
        }
        // ---- adv: 16 cols ----
#pragma unroll
        for (int ii = 0; ii < HK_SUB/64; ii++){
            int k = ja + 64*ii;
            float4 w4 = __ldcs(&Wa4[(size_t)(k0g + k)*4 + c4a]);
#pragma unroll
            for (int b = 0; b < 8; b++){
                float h = Hs[cur][k][b];
                aa[b].x += h*w4.x; aa[b].y += h*w4.y;
                aa[b].z += h*w4.z; aa[b].w += h*w4.w;
            }
        }
        __syncthreads();
        if (st < HK_SPAN/HK_SUB - 1){
#pragma unroll
            for (int q = 0; q < 8; q++) Hs[1-cur][t][q] = rn[q];
            __syncthreads();
        }
    }

    // unpack val accumulators into per-batch float4
    float4 va[8];
#pragma unroll
    for (int p = 0; p < 4; p++){
        float lo, hi;
        unpack2(vacc[p][0], lo, hi); va[2*p].x = lo; va[2*p+1].x = hi;
        unpack2(vacc[p][1], lo, hi); va[2*p].y = lo; va[2*p+1].y = hi;
        unpack2(vacc[p][2], lo, hi); va[2*p].z = lo; va[2*p+1].z = hi;
        unpack2(vacc[p][3], lo, hi); va[2*p].w = lo; va[2*p+1].w = hi;
    }

    float4* red4 = (float4*)&Hs[0][0][0];   // reuse (all threads past final barrier)
    // ---- val reduce: jv pairs (lane offset 16), then across warps ----
#pragma unroll
    for (int b = 0; b < 8; b++) shfl_add(va[b], 16);
    if (l < 16){
#pragma unroll
        for (int b = 0; b < 8; b++) red4[(w*16 + l)*8 + b] = va[b];
    }
    __syncthreads();
    if (t < 128){
        int cc = t & 15, b = t >> 4;
        float4 s = make_float4(0.f,0.f,0.f,0.f);
#pragma unroll
        for (int ww = 0; ww < 8; ww++){
            float4 v = red4[(ww*16 + cc)*8 + b];
            s.x += v.x; s.y += v.y; s.z += v.z; s.w += v.w;
        }
        float* dst = g_valacc + b*64 + cc*4;
        atomicAdd(dst+0, s.x); atomicAdd(dst+1, s.y);
        atomicAdd(dst+2, s.z); atomicAdd(dst+3, s.w);
    }
    __syncthreads();
    // ---- adv reduce: within warp across ja (4,8,16), then warps ----
#pragma unroll
    for (int b = 0; b < 8; b++){
        shfl_add(aa[b], 4); shfl_add(aa[b], 8); shfl_add(aa[b], 16);
    }
    if (l < 4){
#pragma unroll
        for (int b = 0; b < 8; b++) red4[(w*4 + l)*8 + b] = aa[b];
    }
    __syncthreads();
    if (t < 32){
        int cc = t & 3, b = t >> 2;
        float4 s = make_float4(0.f,0.f,0.f,0.f);
#pragma unroll
        for (int ww = 0; ww < 8; ww++){
            float4 v = red4[(ww*4 + cc)*8 + b];
            s.x += v.x; s.y += v.y; s.z += v.z; s.w += v.w;
        }
        float* dst = g_advacc + b*16 + cc*4;
        atomicAdd(dst+0, s.x); atomicAdd(dst+1, s.y);
        atomicAdd(dst+2, s.z); atomicAdd(dst+3, s.w);
    }
}

// ---------- finalize: val MLP + dueling combine + re-zero accumulators -----
__global__ __launch_bounds__(512) void final_kernel(const float* __restrict__ adv_b,
                                                    const float* __restrict__ v1b,
                                                    const float* __restrict__ v2w,
                                                    const float* __restrict__ v2b,
                                                    const float* __restrict__ v3w,
                                                    const float* __restrict__ v3b,
                                                    float* __restrict__ out){
    int t = threadIdx.x;
    __shared__ float v1[512], v2s[512], vS[8], advs[128];
    v1[t] = fmaxf(g_valacc[t] + v1b[t & 63], 0.f);
    g_valacc[t] = 0.f;                                  // re-zero for next call
    if (t < 128){
        advs[t] = fmaxf(g_advacc[t] + adv_b[t & 15], 0.f);
        g_advacc[t] = 0.f;
    }
#pragma unroll
    for (int i = t; i < NNODES; i += 512) g_deg[i] = 0; // re-zero for next call
    __syncthreads();
    {
        int b = t >> 6, c = t & 63;
        float s2 = v2b[c];
        for (int k = 0; k < 64; k++) s2 += v1[b*64 + k] * v2w[k*64 + c];
        v2s[t] = fmaxf(s2, 0.f);
    }
    __syncthreads();
    if (t < 8){
        float s3 = v3b[0];
        for (int k = 0; k < 64; k++) s3 += v2s[t*64 + k] * v3w[k];
        vS[t] = s3;
    }
    __syncthreads();
    if (t < 128){
        int base = t & ~3;
        float mean = 0.25f*(advs[base] + advs[base+1] + advs[base+2] + advs[base+3]);
        out[t] = vS[t >> 4] + advs[t] - mean;
    }
}

// ---------------- launch ----------------
extern "C" void kernel_launch(void* const* d_in, const int* in_sizes, int n_in,
                              void* d_out, int out_size){
    const float* x      = (const float*)d_in[0];
    const void*  edge   = d_in[1];
    const float* W1     = (const float*)d_in[2];
    const float* a_src1 = (const float*)d_in[3];
    const float* a_dst1 = (const float*)d_in[4];
    const float* b1     = (const float*)d_in[5];
    const float* W2     = (const float*)d_in[6];
    const float* a_src2 = (const float*)d_in[7];
    const float* a_dst2 = (const float*)d_in[8];
    const float* b2     = (const float*)d_in[9];
    const float* adv_w  = (const float*)d_in[10];
    const float* adv_b  = (const float*)d_in[11];
    const float* val1_w = (const float*)d_in[12];
    const float* val1_b = (const float*)d_in[13];
    const float* val2_w = (const float*)d_in[14];
    const float* val2_b = (const float*)d_in[15];
    const float* val3_w = (const float*)d_in[16];
    const float* val3_b = (const float*)d_in[17];
    float* out = (float*)d_out;

    prep_kernel<<<66, 512>>>((const int*)edge, W1, a_src1, a_dst1, W2, a_src2, a_dst2);
    scatter_kernel<<<NEDGES/256, 256>>>(edge);          // one-pass bucket CSR
    lin1_kernel<<<NNODES/4, 256>>>(x, W1);

    agg1_kernel<<<NNODES, 64>>>(b1);
    gemm2_kernel<<<dim3(16, 128), 256>>>(W2);
    agg2_kernel<<<NNODES, 256>>>(b2);

    head_kernel<<<1024, 256>>>(val1_w, adv_w);
    final_kernel<<<1, 512>>>(adv_b, val1_b, val2_w, val2_b, val3_w, val3_b, out);
}

// round 14
// speedup vs baseline: 1.0978x; 1.0012x over previous
#include <cuda_runtime.h>
#include <cuda_fp16.h>
#include <cstddef>

#define HEADS  8
#define NNODES 8192
#define NEDGES 131072
#define NEG    0.2f
#define CAP    128          // bucket capacity per dst (max degree ~40 for Binomial(131072,1/8192))

typedef unsigned long long ull;

// ---------------- scratch (static __device__, zero-initialized) -------------
__device__ __half g_h1lin_h[NNODES*64];             // fp16 interchange (1MB)
__device__ float  g_as1[NNODES*HEADS];
__device__ float  g_ad1[NNODES*HEADS];
__device__ float  g_h1[NNODES*64];
__device__ __half g_h2lin_h[(size_t)NNODES*1024];  // 16MB fp16 interchange
__device__ __half g_h2h[(size_t)NNODES*1024];      // 16MB fp16 interchange
__device__ float  g_as2[NNODES*HEADS];
__device__ float  g_ad2[NNODES*HEADS];
__device__ int    g_deg[NNODES];                    // zero at entry; re-zeroed by final
__device__ int    g_srcs[NNODES*CAP];               // 4MB bucket array
__device__ int    g_is64;
__device__ float  g_Ms[64*8];
__device__ float  g_Md[64*8];
__device__ float  g_M1s[16*8];
__device__ float  g_M1d[16*8];
__device__ float  g_valacc[512];                    // zero at entry; re-zeroed by final
__device__ float  g_advacc[128];

struct h4 { __half2 a, b; };

__device__ __forceinline__ float lrelu(float x){ return x > 0.f ? x : NEG*x; }

__device__ __forceinline__ void shfl_add(float4& v, int off){
    v.x += __shfl_down_sync(~0u, v.x, off);
    v.y += __shfl_down_sync(~0u, v.y, off);
    v.z += __shfl_down_sync(~0u, v.z, off);
    v.w += __shfl_down_sync(~0u, v.w, off);
}

// ---- packed fp32x2 helpers (Blackwell) ----
__device__ __forceinline__ ull pack2(float lo, float hi){
    ull r;
    asm("mov.b64 %0, {%1, %2};" : "=l"(r) : "r"(__float_as_uint(lo)), "r"(__float_as_uint(hi)));
    return r;
}
__device__ __forceinline__ void unpack2(ull v, float& lo, float& hi){
    unsigned int a, b;
    asm("mov.b64 {%0, %1}, %2;" : "=r"(a), "=r"(b) : "l"(v));
    lo = __uint_as_float(a); hi = __uint_as_float(b);
}
__device__ __forceinline__ void fma2(ull& d, ull a, ull b){
    asm("fma.rn.f32x2 %0, %1, %2, %0;" : "+l"(d) : "l"(a), "l"(b));
}

// ------ prep: blocks 0..63 = M(W2@a2); block 64 = sniff; block 65 = M1 ------
__global__ __launch_bounds__(512) void prep_kernel(const int* __restrict__ e32,
                                                   const float* __restrict__ W1,
                                                   const float* __restrict__ a_s1,
                                                   const float* __restrict__ a_d1,
                                                   const float* __restrict__ W2,
                                                   const float* __restrict__ a_s2,
                                                   const float* __restrict__ a_d2){
    int t = threadIdx.x;
    int bk = blockIdx.x;
    if (bk == 64){
        __shared__ int nz;
        if (t == 0) nz = 0;
        __syncthreads();
        int v = 0;
        for (int i = t; i < 8192; i += 512) v |= e32[2*i+1];
        if (v) atomicOr(&nz, 1);
        __syncthreads();
        if (t == 0) g_is64 = (nz == 0) ? 1 : 0;
        return;
    }
    if (bk == 65){
        if (t < 128){
            int k = t >> 3, h = t & 7;
            float ms = 0.f, md = 0.f;
#pragma unroll
            for (int c = 0; c < 8; c++){
                float wv = W1[k*64 + h*8 + c];
                ms += wv * a_s1[h*8 + c];
                md += wv * a_d1[h*8 + c];
            }
            g_M1s[k*8 + h] = ms;
            g_M1d[k*8 + h] = md;
        }
        return;
    }
    int k = bk;   // 0..63
    __shared__ float sm[16][4];
    float w1  = W2[k*1024 + t];
    float w2v = W2[k*1024 + 512 + t];
    float p1s = w1  * a_s2[t];
    float p1d = w1  * a_d2[t];
    float p2s = w2v * a_s2[512 + t];
    float p2d = w2v * a_d2[512 + t];
#pragma unroll
    for (int off = 16; off; off >>= 1){
        p1s += __shfl_down_sync(~0u, p1s, off);
        p1d += __shfl_down_sync(~0u, p1d, off);
        p2s += __shfl_down_sync(~0u, p2s, off);
        p2d += __shfl_down_sync(~0u, p2d, off);
    }
    int w = t >> 5, l = t & 31;
    if (l == 0){ sm[w][0]=p1s; sm[w][1]=p1d; sm[w][2]=p2s; sm[w][3]=p2d; }
    __syncthreads();
    if (t < 8){
        float ms, md;
        if (t < 4){
            int b = t*4;
            ms = sm[b][0]+sm[b+1][0]+sm[b+2][0]+sm[b+3][0];
            md = sm[b][1]+sm[b+1][1]+sm[b+2][1]+sm[b+3][1];
        } else {
            int b = (t-4)*4;
            ms = sm[b][2]+sm[b+1][2]+sm[b+2][2]+sm[b+3][2];
            md = sm[b][3]+sm[b+1][3]+sm[b+2][3]+sm[b+3][3];
        }
        g_Ms[k*8 + t] = ms;
        g_Md[k*8 + t] = md;
    }
}

// ---------------- bucket scatter: one-pass CSR (count+place) ----------------
__global__ void scatter_kernel(const void* edge){
    int e = blockIdx.x*256 + threadIdx.x;
    if (e >= NEDGES) return;
    int s, d;
    if (g_is64){
        s = (int)((const long long*)edge)[e];
        d = (int)((const long long*)edge)[NEDGES + e];
    } else {
        s = ((const int*)edge)[e];
        d = ((const int*)edge)[NEDGES + e];
    }
    int pos = atomicAdd(&g_deg[d], 1);
    g_srcs[d*CAP + pos] = s;
}

// ------- layer 1 linear + logits via M1 (no shuffles; 4 nodes/block) -------
__global__ __launch_bounds__(256) void lin1_kernel(const float* __restrict__ x,
                                                   const float* __restrict__ W1){
    __shared__ float Ws[16*64];
    __shared__ float xs[4][16];
    int t = threadIdx.x;
    int nl = t >> 6, tc = t & 63;
    int n = blockIdx.x*4 + nl;
    for (int i = t; i < 1024; i += 256) Ws[i] = W1[i];
    if (t < 64) xs[t >> 4][t & 15] = x[blockIdx.x*64 + t];
    __syncthreads();
    float acc = 0.f;
#pragma unroll
    for (int k = 0; k < 16; k++) acc += xs[nl][k] * Ws[k*64 + tc];
    g_h1lin_h[n*64 + tc] = __float2half(acc);
    // logits: as1[n,h] = x[n,:] . M1s[:,h]  (threads 0..7: as, 8..15: ad)
    if (tc < 16){
        int h = tc & 7;
        const float* M = (tc < 8) ? g_M1s : g_M1d;
        float s = 0.f;
#pragma unroll
        for (int k = 0; k < 16; k++) s += xs[nl][k] * M[k*8 + h];
        if (tc < 8) g_as1[n*8 + h] = s;
        else        g_ad1[n*8 + h] = s;
    }
}

// ------- GAT1 aggregation: warp per node, fp16 gather, syncless ------------
__global__ __launch_bounds__(64) void agg1_kernel(const float* __restrict__ bias){
    int t = threadIdx.x;
    int wp = t >> 5, l = t & 31;
    int d = blockIdx.x*2 + wp;
    int g = l >> 2;                         // head for channels 2l, 2l+1
    int beg = d*CAP, end = beg + g_deg[d];
    float ad = g_ad1[d*8 + g];
    float ws0 = __expf(lrelu(g_as1[d*8 + g] + ad));     // self loop
    float2 h0 = __half22float2(*(const __half2*)(g_h1lin_h + d*64 + 2*l));
    float ax = ws0*h0.x, ay = ws0*h0.y;
    float dp = ws0;
    int i = beg;
    for (; i + 4 <= end; i += 4){
        int s0 = g_srcs[i], s1 = g_srcs[i+1], s2 = g_srcs[i+2], s3 = g_srcs[i+3];
        float w0 = __expf(lrelu(g_as1[s0*8 + g] + ad));
        float w1 = __expf(lrelu(g_as1[s1*8 + g] + ad));
        float w2 = __expf(lrelu(g_as1[s2*8 + g] + ad));
        float w3 = __expf(lrelu(g_as1[s3*8 + g] + ad));
        float2 v0 = __half22float2(*(const __half2*)(g_h1lin_h + s0*64 + 2*l));
        float2 v1 = __half22float2(*(const __half2*)(g_h1lin_h + s1*64 + 2*l));
        float2 v2 = __half22float2(*(const __half2*)(g_h1lin_h + s2*64 + 2*l));
        float2 v3 = __half22float2(*(const __half2*)(g_h1lin_h + s3*64 + 2*l));
        dp += w0 + w1 + w2 + w3;
        ax += w0*v0.x; ay += w0*v0.y;
        ax += w1*v1.x; ay += w1*v1.y;
        ax += w2*v2.x; ay += w2*v2.y;
        ax += w3*v3.x; ay += w3*v3.y;
    }
    for (; i < end; i++){
        int s = g_srcs[i];
        float we = __expf(lrelu(g_as1[s*8 + g] + ad));
        float2 v = __half22float2(*(const __half2*)(g_h1lin_h + s*64 + 2*l));
        dp += we;
        ax += we*v.x; ay += we*v.y;
    }
    float inv = 1.f / (dp + 1e-16f);
    float2 b2 = *(const float2*)(bias + 2*l);
    float h1a = fmaxf(ax*inv + b2.x, 0.f);
    float h1b = fmaxf(ay*inv + b2.y, 0.f);
    float2 o2 = make_float2(h1a, h1b);
    *(float2*)(g_h1 + d*64 + 2*l) = o2;
    // fused alpha2: as2[d,h] = h1[d,:] . Ms[:,h]  (pure warp shuffles)
#pragma unroll
    for (int h = 0; h < 8; h++){
        float vs = h1a*g_Ms[(2*l)*8 + h] + h1b*g_Ms[(2*l+1)*8 + h];
        float vd = h1a*g_Md[(2*l)*8 + h] + h1b*g_Md[(2*l+1)*8 + h];
#pragma unroll
        for (int off = 16; off; off >>= 1){
            vs += __shfl_down_sync(~0u, vs, off);
            vd += __shfl_down_sync(~0u, vd, off);
        }
        if (l == 0){
            g_as2[d*8 + h] = vs;
            g_ad2[d*8 + h] = vd;
        }
    }
}

// ---------------- layer 2 GEMM: h1[8192,64] @ W2[64,1024] -> fp16 ---------
__global__ __launch_bounds__(256) void gemm2_kernel(const float* __restrict__ W2){
    __shared__ float As[64][68];   // [k][m] (transposed)
    __shared__ float Bs[64][68];   // [k][n]
    int t = threadIdx.x;
    int n0 = blockIdx.x*64, m0 = blockIdx.y*64;
#pragma unroll
    for (int q = 0; q < 4; q++){
        int fid = q*256 + t;
        int row = fid >> 4, c4 = fid & 15;
        float4 a = *(const float4*)(g_h1 + (m0+row)*64 + c4*4);
        As[c4*4+0][row] = a.x; As[c4*4+1][row] = a.y;
        As[c4*4+2][row] = a.z; As[c4*4+3][row] = a.w;
        *(float4*)(&Bs[row][c4*4]) = *(const float4*)(W2 + row*1024 + n0 + c4*4);
    }
    __syncthreads();
    int tx = t & 15, ty = t >> 4;
    ull acc[4][2];
#pragma unroll
    for (int i = 0; i < 4; i++){ acc[i][0] = 0ull; acc[i][1] = 0ull; }
#pragma unroll
    for (int k = 0; k < 64; k++){
        float4 a4 = *(const float4*)&As[k][ty*4];
        ull b01 = *(const ull*)&Bs[k][tx*4];
        ull b23 = *(const ull*)&Bs[k][tx*4 + 2];
        ull a0 = pack2(a4.x, a4.x), a1 = pack2(a4.y, a4.y);
        ull a2 = pack2(a4.z, a4.z), a3 = pack2(a4.w, a4.w);
        fma2(acc[0][0], a0, b01); fma2(acc[0][1], a0, b23);
        fma2(acc[1][0], a1, b01); fma2(acc[1][1], a1, b23);
        fma2(acc[2][0], a2, b01); fma2(acc[2][1], a2, b23);
        fma2(acc[3][0], a3, b01); fma2(acc[3][1], a3, b23);
    }
#pragma unroll
    for (int i = 0; i < 4; i++){
        float4 o;
        unpack2(acc[i][0], o.x, o.y);
        unpack2(acc[i][1], o.z, o.w);
        h4 hh;
        hh.a = __floats2half2_rn(o.x, o.y);
        hh.b = __floats2half2_rn(o.z, o.w);
        *(h4*)(g_h2lin_h + (size_t)(m0 + ty*4 + i)*1024 + n0 + tx*4) = hh;
    }
}

// ---------------- GAT2 aggregation (single-pass, fp16 gather) --------------
__global__ __launch_bounds__(256) void agg2_kernel(const float* __restrict__ bias){
    int d = blockIdx.x, t = threadIdx.x;
    int w = t >> 5, l = t & 31;
    __shared__ float adl[8], den_s[8];
    if (t < 8) adl[t] = g_ad2[d*8 + t];
    __syncthreads();
    int beg = d*CAP, end = beg + g_deg[d];
    float ad = adl[w];
    float ws0 = __expf(lrelu(g_as2[d*8 + w] + ad));     // self loop
    int cofs = t*4;
    float4 acc;
    {
        h4 v = *(const h4*)(g_h2lin_h + (size_t)d*1024 + cofs);
        float2 f0 = __half22float2(v.a), f1 = __half22float2(v.b);
        acc.x = ws0*f0.x; acc.y = ws0*f0.y; acc.z = ws0*f1.x; acc.w = ws0*f1.y;
    }
    float dp = ws0;
    int i = beg;
    for (; i + 4 <= end; i += 4){
        int s0 = g_srcs[i], s1 = g_srcs[i+1], s2 = g_srcs[i+2], s3 = g_srcs[i+3];
        float w0 = __expf(lrelu(g_as2[s0*8 + w] + ad));
        float w1 = __expf(lrelu(g_as2[s1*8 + w] + ad));
        float w2 = __expf(lrelu(g_as2[s2*8 + w] + ad));
        float w3 = __expf(lrelu(g_as2[s3*8 + w] + ad));
        h4 p0 = *(const h4*)(g_h2lin_h + (size_t)s0*1024 + cofs);
        h4 p1 = *(const h4*)(g_h2lin_h + (size_t)s1*1024 + cofs);
        h4 p2 = *(const h4*)(g_h2lin_h + (size_t)s2*1024 + cofs);
        h4 p3 = *(const h4*)(g_h2lin_h + (size_t)s3*1024 + cofs);
        dp += w0 + w1 + w2 + w3;
        float2 a0 = __half22float2(p0.a), b0 = __half22float2(p0.b);
        float2 a1 = __half22float2(p1.a), b1 = __half22float2(p1.b);
        float2 a2 = __half22float2(p2.a), b2 = __half22float2(p2.b);
        float2 a3 = __half22float2(p3.a), b3 = __half22float2(p3.b);
        acc.x += w0*a0.x; acc.y += w0*a0.y; acc.z += w0*b0.x; acc.w += w0*b0.y;
        acc.x += w1*a1.x; acc.y += w1*a1.y; acc.z += w1*b1.x; acc.w += w1*b1.y;
        acc.x += w2*a2.x; acc.y += w2*a2.y; acc.z += w2*b2.x; acc.w += w2*b2.y;
        acc.x += w3*a3.x; acc.y += w3*a3.y; acc.z += w3*b3.x; acc.w += w3*b3.y;
    }
    for (; i < end; i++){
        int s = g_srcs[i];
        float we = __expf(lrelu(g_as2[s*8 + w] + ad));
        h4 p = *(const h4*)(g_h2lin_h + (size_t)s*1024 + cofs);
        float2 a0 = __half22float2(p.a), b0 = __half22float2(p.b);
        dp += we;
        acc.x += we*a0.x; acc.y += we*a0.y; acc.z += we*b0.x; acc.w += we*b0.y;
    }
    if (l == 0) den_s[w] = dp + 1e-16f;
    __syncthreads();
    float inv = 1.f / den_s[w];
    float4 b4 = *(const float4*)(bias + cofs);
    h4 o;
    o.a = __floats2half2_rn(fmaxf(acc.x*inv + b4.x, 0.f), fmaxf(acc.y*inv + b4.y, 0.f));
    o.b = __floats2half2_rn(fmaxf(acc.z*inv + b4.z, 0.f), fmaxf(acc.w*inv + b4.w, 0.f));
    *(h4*)(g_h2h + (size_t)d*1024 + cofs) = o;
}

// ---------------- merged dueling heads GEMV (val 64 cols + adv 16 cols) ----
#define HK_SPAN 1024
#define HK_SUB  256
__global__ __launch_bounds__(256) void head_kernel(const float* __restrict__ Wval,
                                                   const float* __restrict__ Wadv){
    __shared__ __align__(16) float Hs[2][HK_SUB][8];   // 16KB, [buf][k][batch]
    int t = threadIdx.x;
    int w = t >> 5, l = t & 31;
    int kbase = blockIdx.x * HK_SPAN;
    int c4v = t & 15, jv = t >> 4;
    int c4a = t & 3,  ja = t >> 2;
    const float4* Wv4 = (const float4*)Wval;
    const float4* Wa4 = (const float4*)Wadv;

    ull vacc[4][4];                 // [batch-pair][col]
#pragma unroll
    for (int p = 0; p < 4; p++)
#pragma unroll
        for (int c = 0; c < 4; c++) vacc[p][c] = 0ull;
    float4 aa[8];
#pragma unroll
    for (int b = 0; b < 8; b++) aa[b] = make_float4(0.f,0.f,0.f,0.f);

    // preload tile 0 (transposed: Hs[k][b])
#pragma unroll
    for (int q = 0; q < 8; q++)
        Hs[0][t][q] = __half2float(g_h2h[(size_t)q*1048576 + kbase + t]);
    __syncthreads();

    for (int st = 0; st < HK_SPAN/HK_SUB; st++){
        int cur = st & 1;
        float rn[8];
        if (st < HK_SPAN/HK_SUB - 1){
#pragma unroll
            for (int q = 0; q < 8; q++)
                rn[q] = __half2float(g_h2h[(size_t)q*1048576 + kbase + (st+1)*HK_SUB + t]);
        }
        int k0g = kbase + st*HK_SUB;
        // ---- val: 64 cols, f32x2 over batch pairs ----
#pragma unroll 4
        for (int ii = 0; ii < HK_SUB/16; ii++){
            int k = jv + 16*ii;
            float4 w4 = __ldcs(&Wv4[(size_t)(k0g + k)*16 + c4v]);
            ull h01 = *(const ull*)&Hs[cur][k][0];
            ull h23 = *(const ull*)&Hs[cur][k][2];
            ull h45 = *(const ull*)&Hs[cur][k][4];
            ull h67 = *(const ull*)&Hs[cur][k][6];
            ull wx = pack2(w4.x, w4.x), wy = pack2(w4.y, w4.y);
            ull wz = pack2(w4.z, w4.z), ww = pack2(w4.w, w4.w);
            fma2(vacc[0][0], h01, wx); fma2(vacc[1][0], h23, wx);
            fma2(vacc[2][0], h45, wx); fma2(vacc[3][0], h67, wx);
            fma2(vacc[0][1], h01, wy); fma2(vacc[1][1], h23, wy);
            fma2(vacc[2][1], h45, wy); fma2(vacc[3][1], h67, wy);
            fma2(vacc[0][2], h01, wz); fma2(vacc[1][2], h23, wz);
            fma2(vacc[2][2], h45, wz); fma2(vacc[3][2], h67, wz);
            fma2(vacc[0][3], h01, ww); fma2(vacc[1][3], h23, ww);
            fma2(vacc[2][3], h45, ww); fma2(vacc[3][3], h67, ww);
        }
        // ---- adv: 16 cols ----
#pragma unroll
        for (int ii = 0; ii < HK_SUB/64; ii++){
            int k = ja + 64*ii;
            float4 w4 = __ldcs(&Wa4[(size_t)(k0g + k)*4 + c4a]);
#pragma unroll
            for (int b = 0; b < 8; b++){
                float h = Hs[cur][k][b];
                aa[b].x += h*w4.x; aa[b].y += h*w4.y;
                aa[b].z += h*w4.z; aa[b].w += h*w4.w;
            }
        }
        __syncthreads();
        if (st < HK_SPAN/HK_SUB - 1){
#pragma unroll
            for (int q = 0; q < 8; q++) Hs[1-cur][t][q] = rn[q];
            __syncthreads();
        }
    }

    // unpack val accumulators into per-batch float4
    float4 va[8];
#pragma unroll
    for (int p = 0; p < 4; p++){
        float lo, hi;
        unpack2(vacc[p][0], lo, hi); va[2*p].x = lo; va[2*p+1].x = hi;
        unpack2(vacc[p][1], lo, hi); va[2*p].y = lo; va[2*p+1].y = hi;
        unpack2(vacc[p][2], lo, hi); va[2*p].z = lo; va[2*p+1].z = hi;
        unpack2(vacc[p][3], lo, hi); va[2*p].w = lo; va[2*p+1].w = hi;
    }

    float4* red4 = (float4*)&Hs[0][0][0];   // reuse (all threads past final barrier)
    // ---- val reduce: jv pairs (lane offset 16), then across warps ----
#pragma unroll
    for (int b = 0; b < 8; b++) shfl_add(va[b], 16);
    if (l < 16){
#pragma unroll
        for (int b = 0; b < 8; b++) red4[(w*16 + l)*8 + b] = va[b];
    }
    __syncthreads();
    if (t < 128){
        int cc = t & 15, b = t >> 4;
        float4 s = make_float4(0.f,0.f,0.f,0.f);
#pragma unroll
        for (int ww = 0; ww < 8; ww++){
            float4 v = red4[(ww*16 + cc)*8 + b];
            s.x += v.x; s.y += v.y; s.z += v.z; s.w += v.w;
        }
        float* dst = g_valacc + b*64 + cc*4;
        atomicAdd(dst+0, s.x); atomicAdd(dst+1, s.y);
        atomicAdd(dst+2, s.z); atomicAdd(dst+3, s.w);
    }
    __syncthreads();
    // ---- adv reduce: within warp across ja (4,8,16), then warps ----
#pragma unroll
    for (int b = 0; b < 8; b++){
        shfl_add(aa[b], 4); shfl_add(aa[b], 8); shfl_add(aa[b], 16);
    }
    if (l < 4){
#pragma unroll
        for (int b = 0; b < 8; b++) red4[(w*4 + l)*8 + b] = aa[b];
    }
    __syncthreads();
    if (t < 32){
        int cc = t & 3, b = t >> 2;
        float4 s = make_float4(0.f,0.f,0.f,0.f);
#pragma unroll
        for (int ww = 0; ww < 8; ww++){
            float4 v = red4[(ww*4 + cc)*8 + b];
            s.x += v.x; s.y += v.y; s.z += v.z; s.w += v.w;
        }
        float* dst = g_advacc + b*16 + cc*4;
        atomicAdd(dst+0, s.x); atomicAdd(dst+1, s.y);
        atomicAdd(dst+2, s.z); atomicAdd(dst+3, s.w);
    }
}

// ---------- finalize: val MLP + dueling combine + re-zero accumulators -----
__global__ __launch_bounds__(512) void final_kernel(const float* __restrict__ adv_b,
                                                    const float* __restrict__ v1b,
                                                    const float* __restrict__ v2w,
                                                    const float* __restrict__ v2b,
                                                    const float* __restrict__ v3w,
                                                    const float* __restrict__ v3b,
                                                    float* __restrict__ out){
    int t = threadIdx.x;
    __shared__ float v1[512], v2s[512], vS[8], advs[128];
    v1[t] = fmaxf(g_valacc[t] + v1b[t & 63], 0.f);
    g_valacc[t] = 0.f;                                  // re-zero for next call
    if (t < 128){
        advs[t] = fmaxf(g_advacc[t] + adv_b[t & 15], 0.f);
        g_advacc[t] = 0.f;
    }
#pragma unroll
    for (int i = t; i < NNODES; i += 512) g_deg[i] = 0; // re-zero for next call
    __syncthreads();
    {
        int b = t >> 6, c = t & 63;
        float s2 = v2b[c];
        for (int k = 0; k < 64; k++) s2 += v1[b*64 + k] * v2w[k*64 + c];
        v2s[t] = fmaxf(s2, 0.f);
    }
    __syncthreads();
    if (t < 8){
        float s3 = v3b[0];
        for (int k = 0; k < 64; k++) s3 += v2s[t*64 + k] * v3w[k];
        vS[t] = s3;
    }
    __syncthreads();
    if (t < 128){
        int base = t & ~3;
        float mean = 0.25f*(advs[base] + advs[base+1] + advs[base+2] + advs[base+3]);
        out[t] = vS[t >> 4] + advs[t] - mean;
    }
}

// ---------------- launch ----------------
extern "C" void kernel_launch(void* const* d_in, const int* in_sizes, int n_in,
                              void* d_out, int out_size){
    const float* x      = (const float*)d_in[0];
    const void*  edge   = d_in[1];
    const float* W1     = (const float*)d_in[2];
    const float* a_src1 = (const float*)d_in[3];
    const float* a_dst1 = (const float*)d_in[4];
    const float* b1     = (const float*)d_in[5];
    const float* W2     = (const float*)d_in[6];
    const float* a_src2 = (const float*)d_in[7];
    const float* a_dst2 = (const float*)d_in[8];
    const float* b2     = (const float*)d_in[9];
    const float* adv_w  = (const float*)d_in[10];
    const float* adv_b  = (const float*)d_in[11];
    const float* val1_w = (const float*)d_in[12];
    const float* val1_b = (const float*)d_in[13];
    const float* val2_w = (const float*)d_in[14];
    const float* val2_b = (const float*)d_in[15];
    const float* val3_w = (const float*)d_in[16];
    const float* val3_b = (const float*)d_in[17];
    float* out = (float*)d_out;

    prep_kernel<<<66, 512>>>((const int*)edge, W1, a_src1, a_dst1, W2, a_src2, a_dst2);
    scatter_kernel<<<NEDGES/256, 256>>>(edge);          // one-pass bucket CSR
    lin1_kernel<<<NNODES/4, 256>>>(x, W1);

    agg1_kernel<<<NNODES/2, 64>>>(b1);
    gemm2_kernel<<<dim3(16, 128), 256>>>(W2);
    agg2_kernel<<<NNODES, 256>>>(b2);

    head_kernel<<<1024, 256>>>(val1_w, adv_w);
    final_kernel<<<1, 512>>>(adv_b, val1_b, val2_w, val2_b, val3_w, val3_b, out);
}